// round 3
// baseline (speedup 1.0000x reference)
#include <cuda_runtime.h>
#include <cuda_bf16.h>
#include <cstdint>

#define BB 16
#define SS 128
#define TT 64
#define EE 768
#define HH 1024
#define VV 32000

// ---------------- device scratch (static, no allocation) ----------------
__device__ __nv_bfloat16 g_xbf[BB * SS * EE];          // x in bf16 (2048,768)
__device__ float         g_xproj[BB * SS * HH];        // x@Wx + b1 (2048,1024) fp32
__device__ __nv_bfloat16 g_WhT[HH * HH];               // attn_Wh^T (1024,1024)
__device__ __nv_bfloat16 g_WxT[HH * EE];               // attn_Wx^T (1024,768)
__device__ __nv_bfloat16 g_Wc0[4096 * 2560];           // [Wih0 | Whh0]
__device__ __nv_bfloat16 g_Wc1[4096 * 2048];           // [Wih1 | Whh1]
__device__ __nv_bfloat16 g_Wc2[4096 * 2048];           // [Wih2 | Whh2]
__device__ __nv_bfloat16 g_fcw[VV * HH];               // fc_W bf16 (32000,1024)
__device__ __nv_bfloat16 g_A0[BB * 2560];              // [emb | ctx | h0]
__device__ __nv_bfloat16 g_A1[BB * 2048];              // [h0_new | h1_prev]
__device__ __nv_bfloat16 g_A2[BB * 2048];              // [h1_new | h2]
__device__ float         g_c[3 * BB * HH];             // LSTM cell states fp32
__device__ float         g_hv[BB * HH];                // h2 @ Wh
__device__ float         g_part[2 * BB * 4096];        // split-K gate partials

// ---------------- prologue kernels ----------------
__global__ void prolog_cvt_x(const float* __restrict__ x) {
    int i = blockIdx.x * 256 + threadIdx.x;
    if (i < BB * SS * EE) g_xbf[i] = __float2bfloat16(x[i]);
}

__global__ void prolog_cvtT_Wx(const float* __restrict__ Wx) {  // (768,1024) -> (1024,768)
    int i = blockIdx.x * 256 + threadIdx.x;
    if (i < EE * HH) {
        int r = i / HH, c = i % HH;
        g_WxT[(long long)c * EE + r] = __float2bfloat16(Wx[i]);
    }
}

__global__ void prolog_cvtT_Wh(const float* __restrict__ Wh) {  // (1024,1024) -> T
    int i = blockIdx.x * 256 + threadIdx.x;
    if (i < HH * HH) {
        int r = i / HH, c = i % HH;
        g_WhT[(long long)c * HH + r] = __float2bfloat16(Wh[i]);
    }
}

__global__ void prolog_cat(const float* __restrict__ Wih, const float* __restrict__ Whh,
                           int c1, int tag) {
    __nv_bfloat16* D = (tag == 0) ? g_Wc0 : (tag == 1) ? g_Wc1 : g_Wc2;
    int C = c1 + HH;
    long long n = (long long)4096 * C;
    long long i = (long long)blockIdx.x * 256 + threadIdx.x;
    if (i < n) {
        int r = (int)(i / C), c = (int)(i % C);
        float v = (c < c1) ? Wih[(long long)r * c1 + c] : Whh[(long long)r * HH + (c - c1)];
        D[i] = __float2bfloat16(v);
    }
}

__global__ void prolog_cvt_fc(const float* __restrict__ fcW) {
    long long i = (long long)blockIdx.x * 256 + threadIdx.x;
    if (i < (long long)VV * HH) g_fcw[i] = __float2bfloat16(fcW[i]);
}

__global__ void prolog_zero() {
    int i = blockIdx.x * 256 + threadIdx.x;
    if (i < 3 * BB * HH) g_c[i] = 0.f;
    __nv_bfloat16 z = __float2bfloat16(0.f);
    if (i < BB * HH) {  // h0 slice of A0
        int b = i >> 10, j = i & 1023;
        g_A0[b * 2560 + 1536 + j] = z;
    }
    if (i < BB * 2048) { g_A1[i] = z; g_A2[i] = z; }
}

// ---------------- generic 16xN bf16 tensor-core GEMM ----------------
// C[m,n] = sum_k A[m,k] * W[n,k]  (+bias[n]).  A row-major (16*gridDim.y, lda),
// W row-major (N, ldb). One warp: 16 output cols; block (128 thr): 64 cols.
__device__ __forceinline__ const __nv_bfloat16* selA(int t) {
    switch (t) {
        case 0: return g_xbf;
        case 1: return g_A0;
        case 2: return g_A1;
        case 3: return g_A2;
        default: return g_A2 + 1024;  // h2 slice
    }
}
__device__ __forceinline__ const __nv_bfloat16* selB(int t) {
    switch (t) {
        case 0: return g_WxT;
        case 1: return g_WhT;
        case 2: return g_Wc0;
        case 3: return g_Wc1;
        case 4: return g_Wc2;
        default: return g_fcw;
    }
}

__device__ __forceinline__ void mma16816(float c[4], uint32_t a0, uint32_t a1, uint32_t a2,
                                         uint32_t a3, uint32_t b0, uint32_t b1) {
    asm volatile(
        "mma.sync.aligned.m16n8k16.row.col.f32.bf16.bf16.f32 "
        "{%0,%1,%2,%3}, {%4,%5,%6,%7}, {%8,%9}, {%0,%1,%2,%3};\n"
        : "+f"(c[0]), "+f"(c[1]), "+f"(c[2]), "+f"(c[3])
        : "r"(a0), "r"(a1), "r"(a2), "r"(a3), "r"(b0), "r"(b1));
}

__global__ __launch_bounds__(128) void gemm_mma(
    int aTag, int lda, int bTag, int ldb,
    int cTag, float* cExt, long long ldc, int partStride,
    const float* __restrict__ bias, int kLen) {
    const __nv_bfloat16* A = selA(aTag);
    const __nv_bfloat16* B = selB(bTag);
    float* C;
    switch (cTag) {
        case 0: C = g_xproj; break;
        case 1: C = g_hv; break;
        case 2: C = g_part; break;
        default: C = cExt; break;
    }
    C += (long long)blockIdx.z * partStride;
    int w = threadIdx.x >> 5, lane = threadIdx.x & 31;
    int g = lane >> 2, tig = lane & 3;
    int m0 = blockIdx.y * 16;
    int n0 = blockIdx.x * 64 + w * 16;
    int kOff = blockIdx.z * kLen;

    float acc0[4] = {0.f, 0.f, 0.f, 0.f};
    float acc1[4] = {0.f, 0.f, 0.f, 0.f};

    const __nv_bfloat16* arow = A + (long long)(m0 + g) * lda + kOff + tig * 2;
    const __nv_bfloat16* ar8  = arow + (long long)8 * lda;
    const __nv_bfloat16* br0  = B + (long long)(n0 + g) * ldb + kOff + tig * 2;
    const __nv_bfloat16* br1  = br0 + (long long)8 * ldb;

#pragma unroll 4
    for (int k = 0; k < kLen; k += 16) {
        uint32_t a0 = *reinterpret_cast<const uint32_t*>(arow + k);
        uint32_t a1 = *reinterpret_cast<const uint32_t*>(ar8 + k);
        uint32_t a2 = *reinterpret_cast<const uint32_t*>(arow + k + 8);
        uint32_t a3 = *reinterpret_cast<const uint32_t*>(ar8 + k + 8);
        uint32_t b00 = *reinterpret_cast<const uint32_t*>(br0 + k);
        uint32_t b01 = *reinterpret_cast<const uint32_t*>(br0 + k + 8);
        uint32_t b10 = *reinterpret_cast<const uint32_t*>(br1 + k);
        uint32_t b11 = *reinterpret_cast<const uint32_t*>(br1 + k + 8);
        mma16816(acc0, a0, a1, a2, a3, b00, b01);
        mma16816(acc1, a0, a1, a2, a3, b10, b11);
    }

    int r0 = m0 + g, r1 = m0 + g + 8;
    {
        int col = n0 + tig * 2;
        float bv0 = bias ? bias[col] : 0.f, bv1 = bias ? bias[col + 1] : 0.f;
        C[(long long)r0 * ldc + col]     = acc0[0] + bv0;
        C[(long long)r0 * ldc + col + 1] = acc0[1] + bv1;
        C[(long long)r1 * ldc + col]     = acc0[2] + bv0;
        C[(long long)r1 * ldc + col + 1] = acc0[3] + bv1;
    }
    {
        int col = n0 + 8 + tig * 2;
        float bv0 = bias ? bias[col] : 0.f, bv1 = bias ? bias[col + 1] : 0.f;
        C[(long long)r0 * ldc + col]     = acc1[0] + bv0;
        C[(long long)r0 * ldc + col + 1] = acc1[1] + bv1;
        C[(long long)r1 * ldc + col]     = acc1[2] + bv0;
        C[(long long)r1 * ldc + col + 1] = acc1[3] + bv1;
    }
}

// ---------------- fused attention: scores + log_softmax + context + layer_in ----------------
__global__ __launch_bounds__(256) void attn_ctx(
    const float* __restrict__ w2, const float* __restrict__ b2,
    const float* __restrict__ x, const int* __restrict__ tseq,
    const float* __restrict__ emb, int t) {
    __shared__ float hv_s[HH];
    __shared__ float w2_s[HH];
    __shared__ float sc[SS];
    __shared__ float red;
    int b = blockIdx.x, tid = threadIdx.x;
    for (int i = tid; i < HH; i += 256) {
        hv_s[i] = g_hv[b * HH + i];
        w2_s[i] = w2[i];
    }
    __syncthreads();
    int w = tid >> 5, lane = tid & 31;
    const float* xp = g_xproj + (long long)b * SS * HH;
    for (int s = w; s < SS; s += 8) {
        const float* row = xp + (long long)s * HH;
        float sum = 0.f;
        for (int k = lane; k < HH; k += 32) {
            float v = row[k] + hv_s[k];
            v = v > 0.f ? v : 0.f;
            sum += v * w2_s[k];
        }
#pragma unroll
        for (int o = 16; o; o >>= 1) sum += __shfl_xor_sync(0xffffffffu, sum, o);
        if (!lane) sc[s] = sum + b2[0];
    }
    __syncthreads();
    if (tid < 32) {
        float m = -1e30f;
        for (int s = tid; s < SS; s += 32) m = fmaxf(m, sc[s]);
#pragma unroll
        for (int o = 16; o; o >>= 1) m = fmaxf(m, __shfl_xor_sync(0xffffffffu, m, o));
        float sum = 0.f;
        for (int s = tid; s < SS; s += 32) sum += expf(sc[s] - m);
#pragma unroll
        for (int o = 16; o; o >>= 1) sum += __shfl_xor_sync(0xffffffffu, sum, o);
        if (!tid) red = m + logf(sum);
    }
    __syncthreads();
    float lse = red;
    if (tid < SS) sc[tid] -= lse;   // log probs
    __syncthreads();
    // context = sum_s lw[s] * x[b,s,:]
    const float* xb = x + (long long)b * SS * EE;
    for (int e = tid; e < EE; e += 256) {
        float acc = 0.f;
#pragma unroll 4
        for (int s = 0; s < SS; s++) acc += sc[s] * xb[(long long)s * EE + e];
        g_A0[b * 2560 + EE + e] = __float2bfloat16(acc);
    }
    int tok = tseq[b * TT + t];
    const float* er = emb + (long long)tok * EE;
    for (int e = tid; e < EE; e += 256)
        g_A0[b * 2560 + e] = __float2bfloat16(er[e]);
}

// ---------------- LSTM cell elementwise ----------------
__global__ __launch_bounds__(256) void lstm_cell(
    const float* __restrict__ bih, const float* __restrict__ bhh, int layer) {
    int idx = blockIdx.x * 256 + threadIdx.x;  // 16384
    int b = idx >> 10, j = idx & 1023;
    const float* p0 = g_part;
    const float* p1 = g_part + BB * 4096;
    int base = b * 4096;
    float gi = p0[base + j]        + p1[base + j]        + bih[j]        + bhh[j];
    float gf = p0[base + 1024 + j] + p1[base + 1024 + j] + bih[1024 + j] + bhh[1024 + j];
    float gg = p0[base + 2048 + j] + p1[base + 2048 + j] + bih[2048 + j] + bhh[2048 + j];
    float go = p0[base + 3072 + j] + p1[base + 3072 + j] + bih[3072 + j] + bhh[3072 + j];
    float si = 1.f / (1.f + expf(-gi));
    float sf = 1.f / (1.f + expf(-gf));
    float so = 1.f / (1.f + expf(-go));
    float* cc = g_c + layer * (BB * HH) + idx;
    float cn = sf * (*cc) + si * tanhf(gg);
    *cc = cn;
    float h = so * tanhf(cn);
    __nv_bfloat16 hb = __float2bfloat16(h);
    if (layer == 0) {
        g_A1[b * 2048 + j] = hb;           // layer1 input (this step)
        g_A0[b * 2560 + 1536 + j] = hb;    // h0 for next step
    } else if (layer == 1) {
        g_A2[b * 2048 + j] = hb;           // layer2 input
        g_A1[b * 2048 + 1024 + j] = hb;    // h1 for next step
    } else {
        g_A2[b * 2048 + 1024 + j] = hb;    // h2: fc this step, hv next step
    }
}

// ---------------- in-place log_softmax over V ----------------
__global__ __launch_bounds__(1024) void lsm_kernel(float* __restrict__ dout, int t) {
    float* row = dout + (long long)blockIdx.x * TT * VV + (long long)t * VV;
    __shared__ float sm[32];
    __shared__ float bc;
    int tid = threadIdx.x, lane = tid & 31, wid = tid >> 5;
    float m = -1e30f;
    for (int v = tid; v < VV; v += 1024) m = fmaxf(m, row[v]);
#pragma unroll
    for (int o = 16; o; o >>= 1) m = fmaxf(m, __shfl_xor_sync(0xffffffffu, m, o));
    if (!lane) sm[wid] = m;
    __syncthreads();
    if (tid < 32) {
        float mm = sm[tid];
#pragma unroll
        for (int o = 16; o; o >>= 1) mm = fmaxf(mm, __shfl_xor_sync(0xffffffffu, mm, o));
        if (!tid) bc = mm;
    }
    __syncthreads();
    m = bc;
    float s = 0.f;
    for (int v = tid; v < VV; v += 1024) s += expf(row[v] - m);
#pragma unroll
    for (int o = 16; o; o >>= 1) s += __shfl_xor_sync(0xffffffffu, s, o);
    __syncthreads();
    if (!lane) sm[wid] = s;
    __syncthreads();
    if (tid < 32) {
        float ss = sm[tid];
#pragma unroll
        for (int o = 16; o; o >>= 1) ss += __shfl_xor_sync(0xffffffffu, ss, o);
        if (!tid) bc = m + logf(ss);
    }
    __syncthreads();
    float lse = bc;
    for (int v = tid; v < VV; v += 1024) row[v] -= lse;
}

// ---------------- host launch ----------------
extern "C" void kernel_launch(void* const* d_in, const int* in_sizes, int n_in,
                              void* d_out, int out_size) {
    const float* x    = (const float*)d_in[0];
    const int*   tseq = (const int*)d_in[1];
    const float* emb  = (const float*)d_in[2];
    const float* Wx   = (const float*)d_in[3];
    const float* Wh   = (const float*)d_in[4];
    const float* b1   = (const float*)d_in[5];
    const float* w2   = (const float*)d_in[6];
    const float* b2   = (const float*)d_in[7];
    const float* fcW  = (const float*)d_in[8];
    const float* fcb  = (const float*)d_in[9];
    const float* Wih0 = (const float*)d_in[10];
    const float* Whh0 = (const float*)d_in[11];
    const float* bih0 = (const float*)d_in[12];
    const float* bhh0 = (const float*)d_in[13];
    const float* Wih1 = (const float*)d_in[14];
    const float* Whh1 = (const float*)d_in[15];
    const float* bih1 = (const float*)d_in[16];
    const float* bhh1 = (const float*)d_in[17];
    const float* Wih2 = (const float*)d_in[18];
    const float* Whh2 = (const float*)d_in[19];
    const float* bih2 = (const float*)d_in[20];
    const float* bhh2 = (const float*)d_in[21];
    float* dout = (float*)d_out;

    // -------- prologue: converts, transposes, concats, zero state, x_proj --------
    prolog_cvt_x<<<(BB * SS * EE + 255) / 256, 256>>>(x);
    prolog_cvtT_Wx<<<(EE * HH + 255) / 256, 256>>>(Wx);
    prolog_cvtT_Wh<<<(HH * HH + 255) / 256, 256>>>(Wh);
    prolog_cat<<<(4096 * 2560 + 255) / 256, 256>>>(Wih0, Whh0, 1536, 0);
    prolog_cat<<<(4096 * 2048 + 255) / 256, 256>>>(Wih1, Whh1, 1024, 1);
    prolog_cat<<<(4096 * 2048 + 255) / 256, 256>>>(Wih2, Whh2, 1024, 2);
    prolog_cvt_fc<<<((long long)VV * HH + 255) / 256, 256>>>(fcW);
    prolog_zero<<<(3 * BB * HH + 255) / 256, 256>>>();
    // x_proj = x @ Wx + b1 : M=2048, K=768, N=1024
    gemm_mma<<<dim3(16, 128, 1), 128>>>(0, EE, 0, EE, 0, nullptr, HH, 0, b1, EE);

    // -------- time loop --------
    for (int t = 0; t < TT; t++) {
        // hv = h2 @ Wh   (K=1024, N=1024)
        gemm_mma<<<dim3(16, 1, 1), 128>>>(4, 2048, 1, HH, 1, nullptr, HH, 0, nullptr, HH);
        // scores + log_softmax + context + layer_in build
        attn_ctx<<<BB, 256>>>(w2, b2, x, tseq, emb, t);
        // layer 0: A0(16,2560) x Wc0(4096,2560), split-K=2
        gemm_mma<<<dim3(64, 1, 2), 128>>>(1, 2560, 2, 2560, 2, nullptr, 4096, BB * 4096,
                                          nullptr, 1280);
        lstm_cell<<<64, 256>>>(bih0, bhh0, 0);
        // layer 1
        gemm_mma<<<dim3(64, 1, 2), 128>>>(2, 2048, 3, 2048, 2, nullptr, 4096, BB * 4096,
                                          nullptr, 1024);
        lstm_cell<<<64, 256>>>(bih1, bhh1, 1);
        // layer 2
        gemm_mma<<<dim3(64, 1, 2), 128>>>(3, 2048, 4, 2048, 2, nullptr, 4096, BB * 4096,
                                          nullptr, 1024);
        lstm_cell<<<64, 256>>>(bih2, bhh2, 2);
        // fc: logits -> d_out[b, t, :]   (N=32000, K=1024, ldc = T*V)
        gemm_mma<<<dim3(500, 1, 1), 128>>>(4, 2048, 5, HH, 3, dout + (long long)t * VV,
                                           (long long)TT * VV, 0, fcb, HH);
        // in-place log_softmax over vocab
        lsm_kernel<<<BB, 1024>>>(dout, t);
    }
}

// round 4
// speedup vs baseline: 1.2624x; 1.2624x over previous
#include <cuda_runtime.h>
#include <cuda_bf16.h>
#include <cstdint>

#define BB 16
#define SS 128
#define TT 64
#define EE 768
#define HH 1024
#define VV 32000

// ---------------- device scratch (static, no allocation) ----------------
__device__ __nv_bfloat16 g_xbf[BB * SS * EE];     // x in bf16 (2048,768)
__device__ float         g_xproj[BB * SS * HH];   // x@Wx + b1 (2048,1024) fp32
// fragment-packed weights: uint4 per (ntile16, kchunk16, lane)
__device__ uint4 g_pWx[(HH / 16) * (EE / 16) * 32];        // attn Wx^T packed (N=1024,K=768)
__device__ uint4 g_pWh[(HH / 16) * (HH / 16) * 32];        // attn Wh^T packed (N=1024,K=1024)
__device__ uint4 g_pWc0[(4096 / 16) * (2560 / 16) * 32];   // [Wih0|Whh0] (N=4096,K=2560)
__device__ uint4 g_pWc1[(4096 / 16) * (2048 / 16) * 32];   // [Wih1|Whh1]
__device__ uint4 g_pWc2[(4096 / 16) * (2048 / 16) * 32];   // [Wih2|Whh2]
__device__ uint4 g_pFc[(VV / 16) * (HH / 16) * 32];        // fc_W (N=32000,K=1024)

__device__ __nv_bfloat16 g_A0[BB * 2560];   // [emb | ctx | h0]
__device__ __nv_bfloat16 g_A1[BB * 2048];   // [h0_new | h1_prev]
__device__ __nv_bfloat16 g_A2[BB * 2048];   // [h1_new | h2]
__device__ float         g_c[3 * BB * HH];  // LSTM cell states fp32
__device__ float         g_hvp[8 * BB * HH];     // h2@Wh split-K partials
__device__ float         g_part[4 * BB * 4096]; // LSTM gate split-K partials

// ---------------- prologue kernels ----------------
__global__ void prolog_cvt_x(const float* __restrict__ x) {
    int i = blockIdx.x * 256 + threadIdx.x;
    if (i < BB * SS * EE) g_xbf[i] = __float2bfloat16(x[i]);
}

__device__ __forceinline__ uint4* pick_dst(int tag) {
    switch (tag) {
        case 0: return g_pWx;
        case 1: return g_pWh;
        case 2: return g_pWc0;
        case 3: return g_pWc1;
        case 4: return g_pWc2;
        default: return g_pFc;
    }
}

// Pack weight into per-warp fragment layout.
// Logical B (N rows, K=K1+K2 cols): col<K1 from s1, else from s2 (width HH).
// tr: s1 stored transposed as (K1, N).
__global__ void pack_w(const float* __restrict__ s1, const float* __restrict__ s2,
                       int N, int K1, int K2, int tr, int dstTag) {
    uint4* dst = pick_dst(dstTag);
    int K = K1 + K2, nch = K >> 4;
    long long idx = (long long)blockIdx.x * 256 + threadIdx.x;
    long long total = (long long)(N >> 4) * nch * 32;
    if (idx >= total) return;
    int lane = (int)(idx & 31);
    long long t = idx >> 5;
    int ch = (int)(t % nch);
    int nt = (int)(t / nch);
    int g = lane >> 2, tig = lane & 3;
    int k = ch * 16 + tig * 2;
    int r0 = nt * 16 + g, r1 = r0 + 8;
    auto ld = [&](int n, int kk) -> float {
        if (kk < K1) return tr ? s1[(long long)kk * N + n] : s1[(long long)n * K1 + kk];
        return s2[(long long)n * HH + (kk - K1)];
    };
    auto p2 = [&](float a, float b) -> unsigned {
        __nv_bfloat162 h = __floats2bfloat162_rn(a, b);  // .x = a (low 16 bits)
        return *reinterpret_cast<unsigned*>(&h);
    };
    uint4 v;
    v.x = p2(ld(r0, k), ld(r0, k + 1));
    v.y = p2(ld(r0, k + 8), ld(r0, k + 9));
    v.z = p2(ld(r1, k), ld(r1, k + 1));
    v.w = p2(ld(r1, k + 8), ld(r1, k + 9));
    dst[idx] = v;
}

__global__ void prolog_zero() {
    int i = blockIdx.x * 256 + threadIdx.x;
    if (i < 3 * BB * HH) g_c[i] = 0.f;
    __nv_bfloat16 z = __float2bfloat16(0.f);
    if (i < BB * HH) {  // h0 slice of A0
        int b = i >> 10, j = i & 1023;
        g_A0[b * 2560 + 1536 + j] = z;
    }
    if (i < BB * 2048) { g_A1[i] = z; g_A2[i] = z; }
}

// ---------------- 16xN bf16 tensor-core GEMM, packed-B ----------------
// C[m,n] = sum_k A[m,k] * W[n,k] (+bias). One warp: 16 n-cols; block (256): 128.
__device__ __forceinline__ const __nv_bfloat16* selA(int t) {
    switch (t) {
        case 0: return g_xbf;
        case 1: return g_A0;
        case 2: return g_A1;
        case 3: return g_A2;
        default: return g_A2 + 1024;  // h2 slice
    }
}

__device__ __forceinline__ void mma16816(float c[4], uint32_t a0, uint32_t a1, uint32_t a2,
                                         uint32_t a3, uint32_t b0, uint32_t b1) {
    asm volatile(
        "mma.sync.aligned.m16n8k16.row.col.f32.bf16.bf16.f32 "
        "{%0,%1,%2,%3}, {%4,%5,%6,%7}, {%8,%9}, {%0,%1,%2,%3};\n"
        : "+f"(c[0]), "+f"(c[1]), "+f"(c[2]), "+f"(c[3])
        : "r"(a0), "r"(a1), "r"(a2), "r"(a3), "r"(b0), "r"(b1));
}

__global__ __launch_bounds__(256) void gemm_v2(
    int aTag, int lda, int bTag, int cTag, float* cExt, long long ldc,
    int partStride, const float* __restrict__ bias, int nCh) {
    const __nv_bfloat16* A = selA(aTag);
    const uint4* B;
    int nchTot;
    switch (bTag) {
        case 0: B = g_pWx;  nchTot = EE / 16;   break;
        case 1: B = g_pWh;  nchTot = HH / 16;   break;
        case 2: B = g_pWc0; nchTot = 2560 / 16; break;
        case 3: B = g_pWc1; nchTot = 2048 / 16; break;
        case 4: B = g_pWc2; nchTot = 2048 / 16; break;
        default: B = g_pFc; nchTot = HH / 16;   break;
    }
    float* C;
    switch (cTag) {
        case 0: C = g_xproj; break;
        case 1: C = g_hvp; break;
        case 2: C = g_part; break;
        default: C = cExt; break;
    }
    C += (long long)blockIdx.z * partStride;

    int w = threadIdx.x >> 5, lane = threadIdx.x & 31;
    int g = lane >> 2, tig = lane & 3;
    int m0 = blockIdx.y * 16;
    int n0 = blockIdx.x * 128 + w * 16;
    int ch0 = blockIdx.z * nCh;

    const uint4* bp = B + ((long long)(n0 >> 4) * nchTot + ch0) * 32 + lane;
    const __nv_bfloat16* arow = A + (long long)(m0 + g) * lda + ch0 * 16 + tig * 2;
    const __nv_bfloat16* ar8 = arow + (long long)8 * lda;

    float acc0[4] = {0.f, 0.f, 0.f, 0.f};
    float acc1[4] = {0.f, 0.f, 0.f, 0.f};

#pragma unroll 4
    for (int c = 0; c < nCh; c++) {
        uint4 b = bp[(long long)c * 32];
        uint32_t a0 = *reinterpret_cast<const uint32_t*>(arow + c * 16);
        uint32_t a1 = *reinterpret_cast<const uint32_t*>(ar8 + c * 16);
        uint32_t a2 = *reinterpret_cast<const uint32_t*>(arow + c * 16 + 8);
        uint32_t a3 = *reinterpret_cast<const uint32_t*>(ar8 + c * 16 + 8);
        mma16816(acc0, a0, a1, a2, a3, b.x, b.y);
        mma16816(acc1, a0, a1, a2, a3, b.z, b.w);
    }

    int r0 = m0 + g, r1 = m0 + g + 8;
    {
        int col = n0 + tig * 2;
        float bv0 = bias ? bias[col] : 0.f, bv1 = bias ? bias[col + 1] : 0.f;
        C[(long long)r0 * ldc + col]     = acc0[0] + bv0;
        C[(long long)r0 * ldc + col + 1] = acc0[1] + bv1;
        C[(long long)r1 * ldc + col]     = acc0[2] + bv0;
        C[(long long)r1 * ldc + col + 1] = acc0[3] + bv1;
    }
    {
        int col = n0 + 8 + tig * 2;
        float bv0 = bias ? bias[col] : 0.f, bv1 = bias ? bias[col + 1] : 0.f;
        C[(long long)r0 * ldc + col]     = acc1[0] + bv0;
        C[(long long)r0 * ldc + col + 1] = acc1[1] + bv1;
        C[(long long)r1 * ldc + col]     = acc1[2] + bv0;
        C[(long long)r1 * ldc + col + 1] = acc1[3] + bv1;
    }
}

// ---------------- fused attention: scores + log_softmax + context + layer_in ----------------
__global__ __launch_bounds__(256) void attn_ctx(
    const float* __restrict__ w2, const float* __restrict__ b2,
    const float* __restrict__ x, const int* __restrict__ tseq,
    const float* __restrict__ emb, int t) {
    __shared__ float hv_s[HH];
    __shared__ float w2_s[HH];
    __shared__ float sc[SS];
    __shared__ float red;
    int b = blockIdx.x, tid = threadIdx.x;
    for (int i = tid; i < HH; i += 256) {
        float s = 0.f;
#pragma unroll
        for (int p = 0; p < 8; p++) s += g_hvp[p * BB * HH + b * HH + i];
        hv_s[i] = s;
        w2_s[i] = w2[i];
    }
    __syncthreads();
    int w = tid >> 5, lane = tid & 31;
    const float* xp = g_xproj + (long long)b * SS * HH;
    for (int s = w; s < SS; s += 8) {
        const float* row = xp + (long long)s * HH;
        float sum = 0.f;
        for (int k = lane; k < HH; k += 32) {
            float v = row[k] + hv_s[k];
            v = v > 0.f ? v : 0.f;
            sum += v * w2_s[k];
        }
#pragma unroll
        for (int o = 16; o; o >>= 1) sum += __shfl_xor_sync(0xffffffffu, sum, o);
        if (!lane) sc[s] = sum + b2[0];
    }
    __syncthreads();
    if (tid < 32) {
        float m = -1e30f;
        for (int s = tid; s < SS; s += 32) m = fmaxf(m, sc[s]);
#pragma unroll
        for (int o = 16; o; o >>= 1) m = fmaxf(m, __shfl_xor_sync(0xffffffffu, m, o));
        float sum = 0.f;
        for (int s = tid; s < SS; s += 32) sum += expf(sc[s] - m);
#pragma unroll
        for (int o = 16; o; o >>= 1) sum += __shfl_xor_sync(0xffffffffu, sum, o);
        if (!tid) red = m + logf(sum);
    }
    __syncthreads();
    float lse = red;
    if (tid < SS) sc[tid] -= lse;  // log probs
    __syncthreads();
    const float* xb = x + (long long)b * SS * EE;
    for (int e = tid; e < EE; e += 256) {
        float acc = 0.f;
#pragma unroll 4
        for (int s = 0; s < SS; s++) acc += sc[s] * xb[(long long)s * EE + e];
        g_A0[b * 2560 + EE + e] = __float2bfloat16(acc);
    }
    int tok = tseq[b * TT + t];
    const float* er = emb + (long long)tok * EE;
    for (int e = tid; e < EE; e += 256)
        g_A0[b * 2560 + e] = __float2bfloat16(er[e]);
}

// ---------------- LSTM cell elementwise (sums 4 split-K partials) ----------------
__global__ __launch_bounds__(256) void lstm_cell(
    const float* __restrict__ bih, const float* __restrict__ bhh, int layer) {
    int idx = blockIdx.x * 256 + threadIdx.x;  // 16384
    int b = idx >> 10, j = idx & 1023;
    float gi = bih[j] + bhh[j];
    float gf = bih[1024 + j] + bhh[1024 + j];
    float gg = bih[2048 + j] + bhh[2048 + j];
    float go = bih[3072 + j] + bhh[3072 + j];
#pragma unroll
    for (int p = 0; p < 4; p++) {
        const float* pp = g_part + p * (BB * 4096) + b * 4096;
        gi += pp[j];
        gf += pp[1024 + j];
        gg += pp[2048 + j];
        go += pp[3072 + j];
    }
    float si = 1.f / (1.f + expf(-gi));
    float sf = 1.f / (1.f + expf(-gf));
    float so = 1.f / (1.f + expf(-go));
    float* cc = g_c + layer * (BB * HH) + idx;
    float cn = sf * (*cc) + si * tanhf(gg);
    *cc = cn;
    float h = so * tanhf(cn);
    __nv_bfloat16 hb = __float2bfloat16(h);
    if (layer == 0) {
        g_A1[b * 2048 + j] = hb;
        g_A0[b * 2560 + 1536 + j] = hb;
    } else if (layer == 1) {
        g_A2[b * 2048 + j] = hb;
        g_A1[b * 2048 + 1024 + j] = hb;
    } else {
        g_A2[b * 2048 + 1024 + j] = hb;
    }
}

// ---------------- in-place log_softmax over V ----------------
__global__ __launch_bounds__(1024) void lsm_kernel(float* __restrict__ dout, int t) {
    float* row = dout + (long long)blockIdx.x * TT * VV + (long long)t * VV;
    __shared__ float sm[32];
    __shared__ float bc;
    int tid = threadIdx.x, lane = tid & 31, wid = tid >> 5;
    float m = -1e30f;
    for (int v = tid; v < VV; v += 1024) m = fmaxf(m, row[v]);
#pragma unroll
    for (int o = 16; o; o >>= 1) m = fmaxf(m, __shfl_xor_sync(0xffffffffu, m, o));
    if (!lane) sm[wid] = m;
    __syncthreads();
    if (tid < 32) {
        float mm = sm[tid];
#pragma unroll
        for (int o = 16; o; o >>= 1) mm = fmaxf(mm, __shfl_xor_sync(0xffffffffu, mm, o));
        if (!tid) bc = mm;
    }
    __syncthreads();
    m = bc;
    float s = 0.f;
    for (int v = tid; v < VV; v += 1024) s += expf(row[v] - m);
#pragma unroll
    for (int o = 16; o; o >>= 1) s += __shfl_xor_sync(0xffffffffu, s, o);
    __syncthreads();
    if (!lane) sm[wid] = s;
    __syncthreads();
    if (tid < 32) {
        float ss = sm[tid];
#pragma unroll
        for (int o = 16; o; o >>= 1) ss += __shfl_xor_sync(0xffffffffu, ss, o);
        if (!tid) bc = m + logf(ss);
    }
    __syncthreads();
    float lse = bc;
    for (int v = tid; v < VV; v += 1024) row[v] -= lse;
}

// ---------------- host launch ----------------
extern "C" void kernel_launch(void* const* d_in, const int* in_sizes, int n_in,
                              void* d_out, int out_size) {
    const float* x    = (const float*)d_in[0];
    const int*   tseq = (const int*)d_in[1];
    const float* emb  = (const float*)d_in[2];
    const float* Wx   = (const float*)d_in[3];
    const float* Wh   = (const float*)d_in[4];
    const float* b1   = (const float*)d_in[5];
    const float* w2   = (const float*)d_in[6];
    const float* b2   = (const float*)d_in[7];
    const float* fcW  = (const float*)d_in[8];
    const float* fcb  = (const float*)d_in[9];
    const float* Wih0 = (const float*)d_in[10];
    const float* Whh0 = (const float*)d_in[11];
    const float* bih0 = (const float*)d_in[12];
    const float* bhh0 = (const float*)d_in[13];
    const float* Wih1 = (const float*)d_in[14];
    const float* Whh1 = (const float*)d_in[15];
    const float* bih1 = (const float*)d_in[16];
    const float* bhh1 = (const float*)d_in[17];
    const float* Wih2 = (const float*)d_in[18];
    const float* Whh2 = (const float*)d_in[19];
    const float* bih2 = (const float*)d_in[20];
    const float* bhh2 = (const float*)d_in[21];
    float* dout = (float*)d_out;

    auto packBlocks = [](long long N, long long K) {
        return (int)((N * K / 8 + 255) / 256);
    };

    // -------- prologue: converts + fragment-packs, zero state, x_proj --------
    prolog_cvt_x<<<(BB * SS * EE + 255) / 256, 256>>>(x);
    pack_w<<<packBlocks(HH, EE), 256>>>(Wx, nullptr, HH, EE, 0, 1, 0);
    pack_w<<<packBlocks(HH, HH), 256>>>(Wh, nullptr, HH, HH, 0, 1, 1);
    pack_w<<<packBlocks(4096, 2560), 256>>>(Wih0, Whh0, 4096, 1536, 1024, 0, 2);
    pack_w<<<packBlocks(4096, 2048), 256>>>(Wih1, Whh1, 4096, 1024, 1024, 0, 3);
    pack_w<<<packBlocks(4096, 2048), 256>>>(Wih2, Whh2, 4096, 1024, 1024, 0, 4);
    pack_w<<<packBlocks(VV, HH), 256>>>(fcW, nullptr, VV, HH, 0, 0, 5);
    prolog_zero<<<(3 * BB * HH + 255) / 256, 256>>>();
    // x_proj = x @ Wx + b1 : M=2048 (grid.y=128), N=1024 (grid.x=8), K=768 (48 chunks)
    gemm_v2<<<dim3(8, 128, 1), 256>>>(0, EE, 0, 0, nullptr, HH, 0, b1, 48);

    // -------- time loop --------
    for (int t = 0; t < TT; t++) {
        // hv = h2 @ Wh : N=1024 (grid.x=8), K=1024 split-K=8 (8 chunks each)
        gemm_v2<<<dim3(8, 1, 8), 256>>>(4, 2048, 1, 1, nullptr, HH, BB * HH, nullptr, 8);
        attn_ctx<<<BB, 256>>>(w2, b2, x, tseq, emb, t);
        // layer 0: K=2560, split-K=4 (40 chunks each), N=4096 (grid.x=32)
        gemm_v2<<<dim3(32, 1, 4), 256>>>(1, 2560, 2, 2, nullptr, 4096, BB * 4096, nullptr, 40);
        lstm_cell<<<64, 256>>>(bih0, bhh0, 0);
        // layer 1: K=2048, split-K=4 (32 chunks each)
        gemm_v2<<<dim3(32, 1, 4), 256>>>(2, 2048, 3, 2, nullptr, 4096, BB * 4096, nullptr, 32);
        lstm_cell<<<64, 256>>>(bih1, bhh1, 1);
        // layer 2
        gemm_v2<<<dim3(32, 1, 4), 256>>>(3, 2048, 4, 2, nullptr, 4096, BB * 4096, nullptr, 32);
        lstm_cell<<<64, 256>>>(bih2, bhh2, 2);
        // fc: N=32000 (grid.x=250), K=1024 (64 chunks) -> d_out[b, t, :]
        gemm_v2<<<dim3(250, 1, 1), 256>>>(4, 2048, 5, 3, dout + (long long)t * VV,
                                          (long long)TT * VV, 0, fcb, 64);
        lsm_kernel<<<BB, 1024>>>(dout, t);
    }
}

// round 5
// speedup vs baseline: 2.5966x; 2.0568x over previous
#include <cuda_runtime.h>
#include <cuda_bf16.h>
#include <cstdint>

#define BB 16
#define SS 128
#define TT 64
#define EE 768
#define HH 1024
#define VV 32000

// ---------------- device scratch (static, no allocation) ----------------
__device__ __nv_bfloat16 g_xbf[BB * SS * EE];        // x bf16 (2048,768)
__device__ __nv_bfloat16 g_xprojbf[BB * SS * HH];    // x@Wx + b1, bf16 (2048,1024)
// fragment-packed weights: uint4 per (ntile16, kchunk16, lane)
__device__ uint4 g_pWx[(HH / 16) * (EE / 16) * 32];
__device__ uint4 g_pWh[(HH / 16) * (HH / 16) * 32];
__device__ uint4 g_pWc0[(4096 / 16) * (2560 / 16) * 32];
__device__ uint4 g_pWc1[(4096 / 16) * (2048 / 16) * 32];
__device__ uint4 g_pWc2[(4096 / 16) * (2048 / 16) * 32];
__device__ uint4 g_pFc[(VV / 16) * (HH / 16) * 32];

__device__ __nv_bfloat16 g_A0[BB * 2560];   // [emb | ctx | h0]
__device__ __nv_bfloat16 g_A1[BB * 2048];   // [h0_new | h1_prev]
__device__ __nv_bfloat16 g_A2[BB * 2048];   // [h1_new | h2]
__device__ float         g_c[3 * BB * HH];  // cell states
__device__ float         g_hvp[8 * BB * HH];      // h2@Wh split-K partials
__device__ float         g_part[8 * BB * 4096];   // LSTM gate split-K partials

// ---------------- prologue ----------------
__global__ void prolog_cvt_x(const float* __restrict__ x) {
    int i = blockIdx.x * 256 + threadIdx.x;
    if (i < BB * SS * EE) g_xbf[i] = __float2bfloat16(x[i]);
}

// all six weights packed by one kernel, flat uint4 index space
__global__ void pack_all(const float* __restrict__ Wx, const float* __restrict__ Wh,
                         const float* __restrict__ Wih0, const float* __restrict__ Whh0,
                         const float* __restrict__ Wih1, const float* __restrict__ Whh1,
                         const float* __restrict__ Wih2, const float* __restrict__ Whh2,
                         const float* __restrict__ fcW) {
    const long long C0 = 98304, C1 = C0 + 131072, C2 = C1 + 1310720,
                    C3 = C2 + 1048576, C4 = C3 + 1048576, C5 = C4 + 4096000;
    long long idx = (long long)blockIdx.x * 256 + threadIdx.x;
    if (idx >= C5) return;
    uint4* dst; const float *s1, *s2 = nullptr;
    int N, K1, K2 = 0, tr; long long base;
    if (idx < C0)      { dst = g_pWx;  s1 = Wx;   N = HH;   K1 = EE;   tr = 1; base = 0; }
    else if (idx < C1) { dst = g_pWh;  s1 = Wh;   N = HH;   K1 = HH;   tr = 1; base = C0; }
    else if (idx < C2) { dst = g_pWc0; s1 = Wih0; s2 = Whh0; N = 4096; K1 = 1536; K2 = 1024; tr = 0; base = C1; }
    else if (idx < C3) { dst = g_pWc1; s1 = Wih1; s2 = Whh1; N = 4096; K1 = 1024; K2 = 1024; tr = 0; base = C2; }
    else if (idx < C4) { dst = g_pWc2; s1 = Wih2; s2 = Whh2; N = 4096; K1 = 1024; K2 = 1024; tr = 0; base = C3; }
    else               { dst = g_pFc;  s1 = fcW;  N = VV;   K1 = HH;   tr = 0; base = C4; }
    long long li = idx - base;
    int nch = (K1 + K2) >> 4;
    int lane = (int)(li & 31);
    long long tt = li >> 5;
    int ch = (int)(tt % nch);
    int nt = (int)(tt / nch);
    int g = lane >> 2, tig = lane & 3;
    int k = ch * 16 + tig * 2;
    int r0 = nt * 16 + g, r1 = r0 + 8;
    auto ld = [&](int n, int kk) -> float {
        if (kk < K1) return tr ? s1[(long long)kk * N + n] : s1[(long long)n * K1 + kk];
        return s2[(long long)n * HH + (kk - K1)];
    };
    auto p2 = [&](float a, float b) -> unsigned {
        __nv_bfloat162 h = __floats2bfloat162_rn(a, b);
        return *reinterpret_cast<unsigned*>(&h);
    };
    uint4 v;
    v.x = p2(ld(r0, k), ld(r0, k + 1));
    v.y = p2(ld(r0, k + 8), ld(r0, k + 9));
    v.z = p2(ld(r1, k), ld(r1, k + 1));
    v.w = p2(ld(r1, k + 8), ld(r1, k + 9));
    dst[li] = v;
}

__global__ void prolog_zero() {
    int i = blockIdx.x * 256 + threadIdx.x;
    if (i < 3 * BB * HH) g_c[i] = 0.f;
    __nv_bfloat16 z = __float2bfloat16(0.f);
    if (i < BB * HH) {
        int b = i >> 10, j = i & 1023;
        g_A0[b * 2560 + 1536 + j] = z;
    }
    if (i < BB * 2048) { g_A1[i] = z; g_A2[i] = z; }
}

// ---------------- 16xN bf16 tensor-core GEMM, packed-B ----------------
__device__ __forceinline__ const __nv_bfloat16* selA(int t) {
    switch (t) {
        case 0: return g_xbf;
        case 1: return g_A0;
        case 2: return g_A1;
        case 3: return g_A2;
        default: return g_A2 + 1024;  // h2 slice
    }
}

__device__ __forceinline__ void mma16816(float c[4], uint32_t a0, uint32_t a1, uint32_t a2,
                                         uint32_t a3, uint32_t b0, uint32_t b1) {
    asm volatile(
        "mma.sync.aligned.m16n8k16.row.col.f32.bf16.bf16.f32 "
        "{%0,%1,%2,%3}, {%4,%5,%6,%7}, {%8,%9}, {%0,%1,%2,%3};\n"
        : "+f"(c[0]), "+f"(c[1]), "+f"(c[2]), "+f"(c[3])
        : "r"(a0), "r"(a1), "r"(a2), "r"(a3), "r"(b0), "r"(b1));
}

// cTag: 0 = g_xprojbf (bf16), 1 = g_hvp, 2 = g_part, 3 = external fp32 (dout)
__global__ __launch_bounds__(256) void gemm_v2(
    int aTag, int lda, int bTag, int cTag, float* cExt, long long ldc,
    int partStride, const float* __restrict__ bias, int nCh) {
    const __nv_bfloat16* A = selA(aTag);
    const uint4* B;
    int nchTot;
    switch (bTag) {
        case 0: B = g_pWx;  nchTot = EE / 16;   break;
        case 1: B = g_pWh;  nchTot = HH / 16;   break;
        case 2: B = g_pWc0; nchTot = 2560 / 16; break;
        case 3: B = g_pWc1; nchTot = 2048 / 16; break;
        case 4: B = g_pWc2; nchTot = 2048 / 16; break;
        default: B = g_pFc; nchTot = HH / 16;   break;
    }
    int w = threadIdx.x >> 5, lane = threadIdx.x & 31;
    int g = lane >> 2, tig = lane & 3;
    int m0 = blockIdx.y * 16;
    int n0 = blockIdx.x * 128 + w * 16;
    int ch0 = blockIdx.z * nCh;

    const uint4* bp = B + ((long long)(n0 >> 4) * nchTot + ch0) * 32 + lane;
    const __nv_bfloat16* arow = A + (long long)(m0 + g) * lda + ch0 * 16 + tig * 2;
    const __nv_bfloat16* ar8 = arow + (long long)8 * lda;

    float acc0[4] = {0.f, 0.f, 0.f, 0.f};
    float acc1[4] = {0.f, 0.f, 0.f, 0.f};

#pragma unroll 8
    for (int c = 0; c < nCh; c++) {
        uint4 b = bp[(long long)c * 32];
        uint32_t a0 = *reinterpret_cast<const uint32_t*>(arow + c * 16);
        uint32_t a1 = *reinterpret_cast<const uint32_t*>(ar8 + c * 16);
        uint32_t a2 = *reinterpret_cast<const uint32_t*>(arow + c * 16 + 8);
        uint32_t a3 = *reinterpret_cast<const uint32_t*>(ar8 + c * 16 + 8);
        mma16816(acc0, a0, a1, a2, a3, b.x, b.y);
        mma16816(acc1, a0, a1, a2, a3, b.z, b.w);
    }

    int r0 = m0 + g, r1 = m0 + g + 8;
    if (cTag == 0) {
        __nv_bfloat16* Cb = g_xprojbf;
        int c0 = n0 + tig * 2, c1 = n0 + 8 + tig * 2;
        float b00 = bias[c0], b01 = bias[c0 + 1], b10 = bias[c1], b11 = bias[c1 + 1];
        Cb[(long long)r0 * ldc + c0]     = __float2bfloat16(acc0[0] + b00);
        Cb[(long long)r0 * ldc + c0 + 1] = __float2bfloat16(acc0[1] + b01);
        Cb[(long long)r1 * ldc + c0]     = __float2bfloat16(acc0[2] + b00);
        Cb[(long long)r1 * ldc + c0 + 1] = __float2bfloat16(acc0[3] + b01);
        Cb[(long long)r0 * ldc + c1]     = __float2bfloat16(acc1[0] + b10);
        Cb[(long long)r0 * ldc + c1 + 1] = __float2bfloat16(acc1[1] + b11);
        Cb[(long long)r1 * ldc + c1]     = __float2bfloat16(acc1[2] + b10);
        Cb[(long long)r1 * ldc + c1 + 1] = __float2bfloat16(acc1[3] + b11);
        return;
    }
    float* C = (cTag == 1) ? g_hvp : (cTag == 2) ? g_part : cExt;
    C += (long long)blockIdx.z * partStride;
    {
        int col = n0 + tig * 2;
        float bv0 = bias ? bias[col] : 0.f, bv1 = bias ? bias[col + 1] : 0.f;
        C[(long long)r0 * ldc + col]     = acc0[0] + bv0;
        C[(long long)r0 * ldc + col + 1] = acc0[1] + bv1;
        C[(long long)r1 * ldc + col]     = acc0[2] + bv0;
        C[(long long)r1 * ldc + col + 1] = acc0[3] + bv1;
    }
    {
        int col = n0 + 8 + tig * 2;
        float bv0 = bias ? bias[col] : 0.f, bv1 = bias ? bias[col + 1] : 0.f;
        C[(long long)r0 * ldc + col]     = acc1[0] + bv0;
        C[(long long)r0 * ldc + col + 1] = acc1[1] + bv1;
        C[(long long)r1 * ldc + col]     = acc1[2] + bv0;
        C[(long long)r1 * ldc + col + 1] = acc1[3] + bv1;
    }
}

// ---------------- fused attention: hv-reduce + scores + log_softmax + context + emb ----------------
__global__ __launch_bounds__(1024) void attn_fused(
    const float* __restrict__ w2, const float* __restrict__ b2,
    const int* __restrict__ tseq, const float* __restrict__ emb, int t) {
    __shared__ float hv_s[HH];
    __shared__ float w2_s[HH];
    __shared__ float sc[SS];
    __shared__ float bc;
    int b = blockIdx.x, tid = threadIdx.x;
    {
        float s = 0.f;
#pragma unroll
        for (int p = 0; p < 8; p++) s += g_hvp[p * BB * HH + b * HH + tid];
        hv_s[tid] = s;
        w2_s[tid] = w2[tid];
    }
    __syncthreads();
    int w = tid >> 5, lane = tid & 31;
#pragma unroll
    for (int rr = 0; rr < 4; rr++) {
        int s = w + rr * 32;
        const __nv_bfloat16* row = g_xprojbf + ((long long)b * SS + s) * HH;
        float sum = 0.f;
#pragma unroll
        for (int it = 0; it < 4; it++) {
            int k0 = it * 256 + lane * 8;
            uint4 v = *reinterpret_cast<const uint4*>(row + k0);
            const __nv_bfloat162* hp = reinterpret_cast<const __nv_bfloat162*>(&v);
#pragma unroll
            for (int j = 0; j < 4; j++) {
                float2 f = __bfloat1622float2(hp[j]);
                int k = k0 + j * 2;
                float a = f.x + hv_s[k];
                float c = f.y + hv_s[k + 1];
                sum += (a > 0.f ? a * w2_s[k] : 0.f) + (c > 0.f ? c * w2_s[k + 1] : 0.f);
            }
        }
#pragma unroll
        for (int o = 16; o; o >>= 1) sum += __shfl_xor_sync(0xffffffffu, sum, o);
        if (!lane) sc[s] = sum + b2[0];
    }
    __syncthreads();
    if (w == 0) {
        float m = -1e30f;
#pragma unroll
        for (int i = 0; i < 4; i++) m = fmaxf(m, sc[lane + i * 32]);
#pragma unroll
        for (int o = 16; o; o >>= 1) m = fmaxf(m, __shfl_xor_sync(0xffffffffu, m, o));
        float su = 0.f;
#pragma unroll
        for (int i = 0; i < 4; i++) su += expf(sc[lane + i * 32] - m);
#pragma unroll
        for (int o = 16; o; o >>= 1) su += __shfl_xor_sync(0xffffffffu, su, o);
        if (!lane) bc = m + logf(su);
    }
    __syncthreads();
    float lse = bc;
    if (tid < SS) sc[tid] -= lse;
    __syncthreads();
    if (tid < EE) {
        const __nv_bfloat16* xb = g_xbf + (long long)b * SS * EE + tid;
        float acc = 0.f;
#pragma unroll 8
        for (int s = 0; s < SS; s++) acc += sc[s] * __bfloat162float(xb[(long long)s * EE]);
        g_A0[b * 2560 + EE + tid] = __float2bfloat16(acc);
        int tok = tseq[b * TT + t];
        g_A0[b * 2560 + tid] = __float2bfloat16(emb[(long long)tok * EE + tid]);
    }
}

// ---------------- LSTM cell elementwise (sums 8 split-K partials) ----------------
__global__ __launch_bounds__(256) void lstm_cell(
    const float* __restrict__ bih, const float* __restrict__ bhh, int layer) {
    int idx = blockIdx.x * 256 + threadIdx.x;  // 16384
    int b = idx >> 10, j = idx & 1023;
    float gi = bih[j] + bhh[j];
    float gf = bih[1024 + j] + bhh[1024 + j];
    float gg = bih[2048 + j] + bhh[2048 + j];
    float go = bih[3072 + j] + bhh[3072 + j];
#pragma unroll
    for (int p = 0; p < 8; p++) {
        const float* pp = g_part + p * (BB * 4096) + b * 4096;
        gi += pp[j];
        gf += pp[1024 + j];
        gg += pp[2048 + j];
        go += pp[3072 + j];
    }
    float si = 1.f / (1.f + expf(-gi));
    float sf = 1.f / (1.f + expf(-gf));
    float so = 1.f / (1.f + expf(-go));
    float* cc = g_c + layer * (BB * HH) + idx;
    float cn = sf * (*cc) + si * tanhf(gg);
    *cc = cn;
    float h = so * tanhf(cn);
    __nv_bfloat16 hb = __float2bfloat16(h);
    if (layer == 0) {
        g_A1[b * 2048 + j] = hb;
        g_A0[b * 2560 + 1536 + j] = hb;
    } else if (layer == 1) {
        g_A2[b * 2048 + j] = hb;
        g_A1[b * 2048 + 1024 + j] = hb;
    } else {
        g_A2[b * 2048 + 1024 + j] = hb;
    }
}

// ---------------- in-place log_softmax over V (float4) ----------------
__global__ __launch_bounds__(1024) void lsm_kernel(float* __restrict__ dout, int t) {
    float4* row = reinterpret_cast<float4*>(dout + (long long)blockIdx.x * TT * VV +
                                            (long long)t * VV);
    const int NV4 = VV / 4;  // 8000
    __shared__ float sm[32];
    __shared__ float bc;
    int tid = threadIdx.x, lane = tid & 31, wid = tid >> 5;
    float m = -1e30f;
    for (int i = tid; i < NV4; i += 1024) {
        float4 v = row[i];
        m = fmaxf(m, fmaxf(fmaxf(v.x, v.y), fmaxf(v.z, v.w)));
    }
#pragma unroll
    for (int o = 16; o; o >>= 1) m = fmaxf(m, __shfl_xor_sync(0xffffffffu, m, o));
    if (!lane) sm[wid] = m;
    __syncthreads();
    if (tid < 32) {
        float mm = sm[tid];
#pragma unroll
        for (int o = 16; o; o >>= 1) mm = fmaxf(mm, __shfl_xor_sync(0xffffffffu, mm, o));
        if (!tid) bc = mm;
    }
    __syncthreads();
    m = bc;
    float s = 0.f;
    for (int i = tid; i < NV4; i += 1024) {
        float4 v = row[i];
        s += expf(v.x - m) + expf(v.y - m) + expf(v.z - m) + expf(v.w - m);
    }
#pragma unroll
    for (int o = 16; o; o >>= 1) s += __shfl_xor_sync(0xffffffffu, s, o);
    __syncthreads();
    if (!lane) sm[wid] = s;
    __syncthreads();
    if (tid < 32) {
        float ss = sm[tid];
#pragma unroll
        for (int o = 16; o; o >>= 1) ss += __shfl_xor_sync(0xffffffffu, ss, o);
        if (!tid) bc = m + logf(ss);
    }
    __syncthreads();
    float lse = bc;
    for (int i = tid; i < NV4; i += 1024) {
        float4 v = row[i];
        v.x -= lse; v.y -= lse; v.z -= lse; v.w -= lse;
        row[i] = v;
    }
}

// ---------------- host launch ----------------
extern "C" void kernel_launch(void* const* d_in, const int* in_sizes, int n_in,
                              void* d_out, int out_size) {
    const float* x    = (const float*)d_in[0];
    const int*   tseq = (const int*)d_in[1];
    const float* emb  = (const float*)d_in[2];
    const float* Wx   = (const float*)d_in[3];
    const float* Wh   = (const float*)d_in[4];
    const float* b1   = (const float*)d_in[5];
    const float* w2   = (const float*)d_in[6];
    const float* b2   = (const float*)d_in[7];
    const float* fcW  = (const float*)d_in[8];
    const float* fcb  = (const float*)d_in[9];
    const float* Wih0 = (const float*)d_in[10];
    const float* Whh0 = (const float*)d_in[11];
    const float* bih0 = (const float*)d_in[12];
    const float* bhh0 = (const float*)d_in[13];
    const float* Wih1 = (const float*)d_in[14];
    const float* Whh1 = (const float*)d_in[15];
    const float* bih1 = (const float*)d_in[16];
    const float* bhh1 = (const float*)d_in[17];
    const float* Wih2 = (const float*)d_in[18];
    const float* Whh2 = (const float*)d_in[19];
    const float* bih2 = (const float*)d_in[20];
    const float* bhh2 = (const float*)d_in[21];
    float* dout = (float*)d_out;

    // side stream + ordering events (created once; creation happens on the
    // non-captured correctness call first)
    static cudaStream_t s2 = nullptr;
    static cudaEvent_t evA = nullptr, evB = nullptr, evEnd = nullptr;
    if (!s2) {
        cudaStreamCreateWithFlags(&s2, cudaStreamNonBlocking);
        cudaEventCreateWithFlags(&evA, cudaEventDisableTiming);
        cudaEventCreateWithFlags(&evB, cudaEventDisableTiming);
        cudaEventCreateWithFlags(&evEnd, cudaEventDisableTiming);
    }

    // -------- prologue --------
    prolog_cvt_x<<<(BB * SS * EE + 255) / 256, 256>>>(x);
    pack_all<<<30208, 256>>>(Wx, Wh, Wih0, Whh0, Wih1, Whh1, Wih2, Whh2, fcW);
    prolog_zero<<<(3 * BB * HH + 255) / 256, 256>>>();
    // x_proj (bf16 out): M=2048, N=1024, K=768 (48 chunks)
    gemm_v2<<<dim3(8, 128, 1), 256>>>(0, EE, 0, 0, nullptr, HH, 0, b1, 48);

    // -------- time loop --------
    for (int t = 0; t < TT; t++) {
        // hv = h2 @ Wh : split-K=8
        gemm_v2<<<dim3(8, 1, 8), 256>>>(4, 2048, 1, 1, nullptr, HH, BB * HH, nullptr, 8);
        attn_fused<<<BB, 1024>>>(w2, b2, tseq, emb, t);
        // layer 0: K=2560 -> 160 chunks, split-K=8 (20 each)
        gemm_v2<<<dim3(32, 1, 8), 256>>>(1, 2560, 2, 2, nullptr, 4096, BB * 4096, nullptr, 20);
        lstm_cell<<<64, 256>>>(bih0, bhh0, 0);
        // layer 1: K=2048 -> 128 chunks, split-K=8 (16 each)
        gemm_v2<<<dim3(32, 1, 8), 256>>>(2, 2048, 3, 2, nullptr, 4096, BB * 4096, nullptr, 16);
        lstm_cell<<<64, 256>>>(bih1, bhh1, 1);
        // layer 2
        gemm_v2<<<dim3(32, 1, 8), 256>>>(3, 2048, 4, 2, nullptr, 4096, BB * 4096, nullptr, 16);
        // cell2 overwrites h2 -> must wait for previous step's fc (reads h2)
        if (t > 0) cudaStreamWaitEvent(0, evB, 0);
        lstm_cell<<<64, 256>>>(bih2, bhh2, 2);

        // fork fc + lsm onto side stream (depends only on cell2 of this step)
        cudaEventRecord(evA, 0);
        cudaStreamWaitEvent(s2, evA, 0);
        gemm_v2<<<dim3(250, 1, 1), 256, 0, s2>>>(4, 2048, 5, 3, dout + (long long)t * VV,
                                                 (long long)TT * VV, 0, fcb, 64);
        cudaEventRecord(evB, s2);
        lsm_kernel<<<BB, 1024, 0, s2>>>(dout, t);
    }
    // join side stream back before capture ends
    cudaEventRecord(evEnd, s2);
    cudaStreamWaitEvent(0, evEnd, 0);
}

// round 6
// speedup vs baseline: 3.2707x; 1.2596x over previous
#include <cuda_runtime.h>
#include <cuda_bf16.h>
#include <cstdint>

#define BB 16
#define SS 128
#define TT 64
#define EE 768
#define HH 1024
#define VV 32000

// ---------------- device scratch (static, no allocation) ----------------
__device__ __nv_bfloat16 g_xbf[BB * SS * EE];        // x bf16 (2048,768)
__device__ __nv_bfloat16 g_xprojbf[BB * SS * HH];    // x@Wx + b1, bf16 (2048,1024)
// fragment-packed weights: uint4 per (ntile16, kchunk16, lane)
__device__ uint4 g_pWx[(HH / 16) * (EE / 16) * 32];
__device__ uint4 g_pWh[(HH / 16) * (HH / 16) * 32];
__device__ uint4 g_pWc0[(4096 / 16) * (2560 / 16) * 32];
__device__ uint4 g_pWc1[(4096 / 16) * (2048 / 16) * 32];
__device__ uint4 g_pWc2[(4096 / 16) * (2048 / 16) * 32];
__device__ uint4 g_pFc[(VV / 16) * (HH / 16) * 32];

__device__ __nv_bfloat16 g_A0[BB * 2560];   // [emb | ctx | h0]
__device__ __nv_bfloat16 g_A1[BB * 2048];   // [h0_new | h1_prev]
__device__ __nv_bfloat16 g_A2[BB * 2048];   // [h1_new | h2]
__device__ float         g_c[3 * BB * HH];  // cell states
__device__ float         g_hvp[8 * BB * HH];      // h2@Wh split-K partials
__device__ float         g_part[8 * BB * 4096];   // LSTM gate split-K partials

// ---------------- prologue ----------------
__global__ void prolog_cvt_x(const float* __restrict__ x) {
    int i = blockIdx.x * 256 + threadIdx.x;
    if (i < BB * SS * EE) g_xbf[i] = __float2bfloat16(x[i]);
}

// all six weights packed by one kernel, flat uint4 index space
__global__ void pack_all(const float* __restrict__ Wx, const float* __restrict__ Wh,
                         const float* __restrict__ Wih0, const float* __restrict__ Whh0,
                         const float* __restrict__ Wih1, const float* __restrict__ Whh1,
                         const float* __restrict__ Wih2, const float* __restrict__ Whh2,
                         const float* __restrict__ fcW) {
    const long long C0 = 98304, C1 = C0 + 131072, C2 = C1 + 1310720,
                    C3 = C2 + 1048576, C4 = C3 + 1048576, C5 = C4 + 4096000;
    long long idx = (long long)blockIdx.x * 256 + threadIdx.x;
    if (idx >= C5) return;
    uint4* dst; const float *s1, *s2 = nullptr;
    int N, K1, K2 = 0, tr; long long base;
    if (idx < C0)      { dst = g_pWx;  s1 = Wx;   N = HH;   K1 = EE;   tr = 1; base = 0; }
    else if (idx < C1) { dst = g_pWh;  s1 = Wh;   N = HH;   K1 = HH;   tr = 1; base = C0; }
    else if (idx < C2) { dst = g_pWc0; s1 = Wih0; s2 = Whh0; N = 4096; K1 = 1536; K2 = 1024; tr = 0; base = C1; }
    else if (idx < C3) { dst = g_pWc1; s1 = Wih1; s2 = Whh1; N = 4096; K1 = 1024; K2 = 1024; tr = 0; base = C2; }
    else if (idx < C4) { dst = g_pWc2; s1 = Wih2; s2 = Whh2; N = 4096; K1 = 1024; K2 = 1024; tr = 0; base = C3; }
    else               { dst = g_pFc;  s1 = fcW;  N = VV;   K1 = HH;   tr = 0; base = C4; }
    long long li = idx - base;
    int nch = (K1 + K2) >> 4;
    int lane = (int)(li & 31);
    long long tt = li >> 5;
    int ch = (int)(tt % nch);
    int nt = (int)(tt / nch);
    int g = lane >> 2, tig = lane & 3;
    int k = ch * 16 + tig * 2;
    int r0 = nt * 16 + g, r1 = r0 + 8;
    auto ld = [&](int n, int kk) -> float {
        if (kk < K1) return tr ? s1[(long long)kk * N + n] : s1[(long long)n * K1 + kk];
        return s2[(long long)n * HH + (kk - K1)];
    };
    auto p2 = [&](float a, float b) -> unsigned {
        __nv_bfloat162 h = __floats2bfloat162_rn(a, b);
        return *reinterpret_cast<unsigned*>(&h);
    };
    uint4 v;
    v.x = p2(ld(r0, k), ld(r0, k + 1));
    v.y = p2(ld(r0, k + 8), ld(r0, k + 9));
    v.z = p2(ld(r1, k), ld(r1, k + 1));
    v.w = p2(ld(r1, k + 8), ld(r1, k + 9));
    dst[li] = v;
}

__global__ void prolog_zero() {
    int i = blockIdx.x * 256 + threadIdx.x;
    if (i < 3 * BB * HH) g_c[i] = 0.f;
    __nv_bfloat16 z = __float2bfloat16(0.f);
    if (i < BB * HH) {
        int b = i >> 10, j = i & 1023;
        g_A0[b * 2560 + 1536 + j] = z;
    }
    if (i < BB * 2048) { g_A1[i] = z; g_A2[i] = z; }
}

// ---------------- 16xN bf16 tensor-core GEMM, packed-B, smem-staged A ----------------
__device__ __forceinline__ const __nv_bfloat16* selA(int t) {
    switch (t) {
        case 0: return g_xbf;
        case 1: return g_A0;
        case 2: return g_A1;
        case 3: return g_A2;
        default: return g_A2 + 1024;  // h2 slice
    }
}

__device__ __forceinline__ void mma16816(float c[4], uint32_t a0, uint32_t a1, uint32_t a2,
                                         uint32_t a3, uint32_t b0, uint32_t b1) {
    asm volatile(
        "mma.sync.aligned.m16n8k16.row.col.f32.bf16.bf16.f32 "
        "{%0,%1,%2,%3}, {%4,%5,%6,%7}, {%8,%9}, {%0,%1,%2,%3};\n"
        : "+f"(c[0]), "+f"(c[1]), "+f"(c[2]), "+f"(c[3])
        : "r"(a0), "r"(a1), "r"(a2), "r"(a3), "r"(b0), "r"(b1));
}

#define APAD 8
#define AMAXC (64 * 16)  // max k-slice per block (fc: 64 chunks)

// cTag: 0 = g_xprojbf (bf16), 1 = g_hvp, 2 = g_part, 3 = external fp32 (dout)
__global__ __launch_bounds__(256) void gemm_v3(
    int aTag, int lda, int bTag, int cTag, float* cExt, long long ldc,
    int partStride, const float* __restrict__ bias, int nCh) {
    __shared__ __nv_bfloat16 s_a[16][AMAXC + APAD];
    const __nv_bfloat16* A = selA(aTag);
    const uint4* B;
    int nchTot;
    switch (bTag) {
        case 0: B = g_pWx;  nchTot = EE / 16;   break;
        case 1: B = g_pWh;  nchTot = HH / 16;   break;
        case 2: B = g_pWc0; nchTot = 2560 / 16; break;
        case 3: B = g_pWc1; nchTot = 2048 / 16; break;
        case 4: B = g_pWc2; nchTot = 2048 / 16; break;
        default: B = g_pFc; nchTot = HH / 16;   break;
    }
    int w = threadIdx.x >> 5, lane = threadIdx.x & 31;
    int g = lane >> 2, tig = lane & 3;
    int m0 = blockIdx.y * 16;
    int n0 = blockIdx.x * 128 + w * 16;
    int ch0 = blockIdx.z * nCh;

    // ---- stage A slice (16 x nCh*16) into padded smem, coalesced uint4 ----
    {
        int cols4 = nCh * 2;  // uint4 per row
        for (int idx = threadIdx.x; idx < 16 * cols4; idx += 256) {
            int r = idx / cols4, cc = idx % cols4;
            uint4 v = *reinterpret_cast<const uint4*>(
                A + (long long)(m0 + r) * lda + ch0 * 16 + cc * 8);
            *reinterpret_cast<uint4*>(&s_a[r][cc * 8]) = v;
        }
    }
    __syncthreads();

    const uint4* bp = B + ((long long)(n0 >> 4) * nchTot + ch0) * 32 + lane;

    float acc0[4] = {0.f, 0.f, 0.f, 0.f};
    float acc1[4] = {0.f, 0.f, 0.f, 0.f};

#pragma unroll 8
    for (int c = 0; c < nCh; c++) {
        uint4 b = bp[(long long)c * 32];
        uint32_t a0 = *reinterpret_cast<const uint32_t*>(&s_a[g][c * 16 + tig * 2]);
        uint32_t a1 = *reinterpret_cast<const uint32_t*>(&s_a[g + 8][c * 16 + tig * 2]);
        uint32_t a2 = *reinterpret_cast<const uint32_t*>(&s_a[g][c * 16 + 8 + tig * 2]);
        uint32_t a3 = *reinterpret_cast<const uint32_t*>(&s_a[g + 8][c * 16 + 8 + tig * 2]);
        mma16816(acc0, a0, a1, a2, a3, b.x, b.y);
        mma16816(acc1, a0, a1, a2, a3, b.z, b.w);
    }

    int r0 = m0 + g, r1 = m0 + g + 8;
    if (cTag == 0) {
        __nv_bfloat16* Cb = g_xprojbf;
        int c0 = n0 + tig * 2, c1 = n0 + 8 + tig * 2;
        float b00 = bias[c0], b01 = bias[c0 + 1], b10 = bias[c1], b11 = bias[c1 + 1];
        Cb[(long long)r0 * ldc + c0]     = __float2bfloat16(acc0[0] + b00);
        Cb[(long long)r0 * ldc + c0 + 1] = __float2bfloat16(acc0[1] + b01);
        Cb[(long long)r1 * ldc + c0]     = __float2bfloat16(acc0[2] + b00);
        Cb[(long long)r1 * ldc + c0 + 1] = __float2bfloat16(acc0[3] + b01);
        Cb[(long long)r0 * ldc + c1]     = __float2bfloat16(acc1[0] + b10);
        Cb[(long long)r0 * ldc + c1 + 1] = __float2bfloat16(acc1[1] + b11);
        Cb[(long long)r1 * ldc + c1]     = __float2bfloat16(acc1[2] + b10);
        Cb[(long long)r1 * ldc + c1 + 1] = __float2bfloat16(acc1[3] + b11);
        return;
    }
    float* C = (cTag == 1) ? g_hvp : (cTag == 2) ? g_part : cExt;
    C += (long long)blockIdx.z * partStride;
    {
        int col = n0 + tig * 2;
        float bv0 = bias ? bias[col] : 0.f, bv1 = bias ? bias[col + 1] : 0.f;
        C[(long long)r0 * ldc + col]     = acc0[0] + bv0;
        C[(long long)r0 * ldc + col + 1] = acc0[1] + bv1;
        C[(long long)r1 * ldc + col]     = acc0[2] + bv0;
        C[(long long)r1 * ldc + col + 1] = acc0[3] + bv1;
    }
    {
        int col = n0 + 8 + tig * 2;
        float bv0 = bias ? bias[col] : 0.f, bv1 = bias ? bias[col + 1] : 0.f;
        C[(long long)r0 * ldc + col]     = acc1[0] + bv0;
        C[(long long)r0 * ldc + col + 1] = acc1[1] + bv1;
        C[(long long)r1 * ldc + col]     = acc1[2] + bv0;
        C[(long long)r1 * ldc + col + 1] = acc1[3] + bv1;
    }
}

// ---------------- fused attention: hv-reduce + scores + log_softmax + context + emb ----------------
__global__ __launch_bounds__(1024) void attn_fused(
    const float* __restrict__ w2, const float* __restrict__ b2,
    const int* __restrict__ tseq, const float* __restrict__ emb, int t) {
    __shared__ float hv_s[HH];
    __shared__ float w2_s[HH];
    __shared__ float sc[SS];
    __shared__ float bc;
    int b = blockIdx.x, tid = threadIdx.x;
    {
        float s = 0.f;
#pragma unroll
        for (int p = 0; p < 8; p++) s += g_hvp[p * BB * HH + b * HH + tid];
        hv_s[tid] = s;
        w2_s[tid] = w2[tid];
    }
    __syncthreads();
    int w = tid >> 5, lane = tid & 31;
#pragma unroll
    for (int rr = 0; rr < 4; rr++) {
        int s = w + rr * 32;
        const __nv_bfloat16* row = g_xprojbf + ((long long)b * SS + s) * HH;
        float sum = 0.f;
#pragma unroll
        for (int it = 0; it < 4; it++) {
            int k0 = it * 256 + lane * 8;
            uint4 v = *reinterpret_cast<const uint4*>(row + k0);
            const __nv_bfloat162* hp = reinterpret_cast<const __nv_bfloat162*>(&v);
#pragma unroll
            for (int j = 0; j < 4; j++) {
                float2 f = __bfloat1622float2(hp[j]);
                int k = k0 + j * 2;
                float a = f.x + hv_s[k];
                float c = f.y + hv_s[k + 1];
                sum += (a > 0.f ? a * w2_s[k] : 0.f) + (c > 0.f ? c * w2_s[k + 1] : 0.f);
            }
        }
#pragma unroll
        for (int o = 16; o; o >>= 1) sum += __shfl_xor_sync(0xffffffffu, sum, o);
        if (!lane) sc[s] = sum + b2[0];
    }
    __syncthreads();
    if (w == 0) {
        float m = -1e30f;
#pragma unroll
        for (int i = 0; i < 4; i++) m = fmaxf(m, sc[lane + i * 32]);
#pragma unroll
        for (int o = 16; o; o >>= 1) m = fmaxf(m, __shfl_xor_sync(0xffffffffu, m, o));
        float su = 0.f;
#pragma unroll
        for (int i = 0; i < 4; i++) su += expf(sc[lane + i * 32] - m);
#pragma unroll
        for (int o = 16; o; o >>= 1) su += __shfl_xor_sync(0xffffffffu, su, o);
        if (!lane) bc = m + logf(su);
    }
    __syncthreads();
    float lse = bc;
    if (tid < SS) sc[tid] -= lse;
    __syncthreads();
    if (tid < EE) {
        const __nv_bfloat16* xb = g_xbf + (long long)b * SS * EE + tid;
        float acc = 0.f;
#pragma unroll 8
        for (int s = 0; s < SS; s++) acc += sc[s] * __bfloat162float(xb[(long long)s * EE]);
        g_A0[b * 2560 + EE + tid] = __float2bfloat16(acc);
        int tok = tseq[b * TT + t];
        g_A0[b * 2560 + tid] = __float2bfloat16(emb[(long long)tok * EE + tid]);
    }
}

// ---------------- LSTM cell elementwise (sums 8 split-K partials) ----------------
__global__ __launch_bounds__(256) void lstm_cell(
    const float* __restrict__ bih, const float* __restrict__ bhh, int layer) {
    int idx = blockIdx.x * 256 + threadIdx.x;  // 16384
    int b = idx >> 10, j = idx & 1023;
    float gi = bih[j] + bhh[j];
    float gf = bih[1024 + j] + bhh[1024 + j];
    float gg = bih[2048 + j] + bhh[2048 + j];
    float go = bih[3072 + j] + bhh[3072 + j];
#pragma unroll
    for (int p = 0; p < 8; p++) {
        const float* pp = g_part + p * (BB * 4096) + b * 4096;
        gi += pp[j];
        gf += pp[1024 + j];
        gg += pp[2048 + j];
        go += pp[3072 + j];
    }
    float si = 1.f / (1.f + expf(-gi));
    float sf = 1.f / (1.f + expf(-gf));
    float so = 1.f / (1.f + expf(-go));
    float* cc = g_c + layer * (BB * HH) + idx;
    float cn = sf * (*cc) + si * tanhf(gg);
    *cc = cn;
    float h = so * tanhf(cn);
    __nv_bfloat16 hb = __float2bfloat16(h);
    if (layer == 0) {
        g_A1[b * 2048 + j] = hb;
        g_A0[b * 2560 + 1536 + j] = hb;
    } else if (layer == 1) {
        g_A2[b * 2048 + j] = hb;
        g_A1[b * 2048 + 1024 + j] = hb;
    } else {
        g_A2[b * 2048 + 1024 + j] = hb;
    }
}

// ---------------- in-place log_softmax over V (float4) ----------------
__global__ __launch_bounds__(1024) void lsm_kernel(float* __restrict__ dout, int t) {
    float4* row = reinterpret_cast<float4*>(dout + (long long)blockIdx.x * TT * VV +
                                            (long long)t * VV);
    const int NV4 = VV / 4;  // 8000
    __shared__ float sm[32];
    __shared__ float bc;
    int tid = threadIdx.x, lane = tid & 31, wid = tid >> 5;
    float m = -1e30f;
    for (int i = tid; i < NV4; i += 1024) {
        float4 v = row[i];
        m = fmaxf(m, fmaxf(fmaxf(v.x, v.y), fmaxf(v.z, v.w)));
    }
#pragma unroll
    for (int o = 16; o; o >>= 1) m = fmaxf(m, __shfl_xor_sync(0xffffffffu, m, o));
    if (!lane) sm[wid] = m;
    __syncthreads();
    if (tid < 32) {
        float mm = sm[tid];
#pragma unroll
        for (int o = 16; o; o >>= 1) mm = fmaxf(mm, __shfl_xor_sync(0xffffffffu, mm, o));
        if (!tid) bc = mm;
    }
    __syncthreads();
    m = bc;
    float s = 0.f;
    for (int i = tid; i < NV4; i += 1024) {
        float4 v = row[i];
        s += expf(v.x - m) + expf(v.y - m) + expf(v.z - m) + expf(v.w - m);
    }
#pragma unroll
    for (int o = 16; o; o >>= 1) s += __shfl_xor_sync(0xffffffffu, s, o);
    __syncthreads();
    if (!lane) sm[wid] = s;
    __syncthreads();
    if (tid < 32) {
        float ss = sm[tid];
#pragma unroll
        for (int o = 16; o; o >>= 1) ss += __shfl_xor_sync(0xffffffffu, ss, o);
        if (!tid) bc = m + logf(ss);
    }
    __syncthreads();
    float lse = bc;
    for (int i = tid; i < NV4; i += 1024) {
        float4 v = row[i];
        v.x -= lse; v.y -= lse; v.z -= lse; v.w -= lse;
        row[i] = v;
    }
}

// ---------------- host launch ----------------
extern "C" void kernel_launch(void* const* d_in, const int* in_sizes, int n_in,
                              void* d_out, int out_size) {
    const float* x    = (const float*)d_in[0];
    const int*   tseq = (const int*)d_in[1];
    const float* emb  = (const float*)d_in[2];
    const float* Wx   = (const float*)d_in[3];
    const float* Wh   = (const float*)d_in[4];
    const float* b1   = (const float*)d_in[5];
    const float* w2   = (const float*)d_in[6];
    const float* b2   = (const float*)d_in[7];
    const float* fcW  = (const float*)d_in[8];
    const float* fcb  = (const float*)d_in[9];
    const float* Wih0 = (const float*)d_in[10];
    const float* Whh0 = (const float*)d_in[11];
    const float* bih0 = (const float*)d_in[12];
    const float* bhh0 = (const float*)d_in[13];
    const float* Wih1 = (const float*)d_in[14];
    const float* Whh1 = (const float*)d_in[15];
    const float* bih1 = (const float*)d_in[16];
    const float* bhh1 = (const float*)d_in[17];
    const float* Wih2 = (const float*)d_in[18];
    const float* Whh2 = (const float*)d_in[19];
    const float* bih2 = (const float*)d_in[20];
    const float* bhh2 = (const float*)d_in[21];
    float* dout = (float*)d_out;

    static cudaStream_t s2 = nullptr;
    static cudaEvent_t evA = nullptr, evB = nullptr, evEnd = nullptr;
    if (!s2) {
        cudaStreamCreateWithFlags(&s2, cudaStreamNonBlocking);
        cudaEventCreateWithFlags(&evA, cudaEventDisableTiming);
        cudaEventCreateWithFlags(&evB, cudaEventDisableTiming);
        cudaEventCreateWithFlags(&evEnd, cudaEventDisableTiming);
    }

    // -------- prologue --------
    prolog_cvt_x<<<(BB * SS * EE + 255) / 256, 256>>>(x);
    pack_all<<<30208, 256>>>(Wx, Wh, Wih0, Whh0, Wih1, Whh1, Wih2, Whh2, fcW);
    prolog_zero<<<(3 * BB * HH + 255) / 256, 256>>>();
    // x_proj (bf16 out): M=2048, N=1024, K=768 (48 chunks)
    gemm_v3<<<dim3(8, 128, 1), 256>>>(0, EE, 0, 0, nullptr, HH, 0, b1, 48);

    // -------- time loop --------
    for (int t = 0; t < TT; t++) {
        // hv = h2 @ Wh : split-K=8
        gemm_v3<<<dim3(8, 1, 8), 256>>>(4, 2048, 1, 1, nullptr, HH, BB * HH, nullptr, 8);
        attn_fused<<<BB, 1024>>>(w2, b2, tseq, emb, t);
        // layer 0: K=2560 -> 160 chunks, split-K=8 (20 each)
        gemm_v3<<<dim3(32, 1, 8), 256>>>(1, 2560, 2, 2, nullptr, 4096, BB * 4096, nullptr, 20);
        lstm_cell<<<64, 256>>>(bih0, bhh0, 0);
        // layer 1: K=2048 -> 128 chunks, split-K=8 (16 each)
        gemm_v3<<<dim3(32, 1, 8), 256>>>(2, 2048, 3, 2, nullptr, 4096, BB * 4096, nullptr, 16);
        lstm_cell<<<64, 256>>>(bih1, bhh1, 1);
        // layer 2
        gemm_v3<<<dim3(32, 1, 8), 256>>>(3, 2048, 4, 2, nullptr, 4096, BB * 4096, nullptr, 16);
        // cell2 overwrites h2 -> must wait for previous step's fc (reads h2)
        if (t > 0) cudaStreamWaitEvent(0, evB, 0);
        lstm_cell<<<64, 256>>>(bih2, bhh2, 2);

        // fork fc + lsm onto side stream (depends only on cell2 of this step)
        cudaEventRecord(evA, 0);
        cudaStreamWaitEvent(s2, evA, 0);
        gemm_v3<<<dim3(250, 1, 1), 256, 0, s2>>>(4, 2048, 5, 3, dout + (long long)t * VV,
                                                 (long long)TT * VV, 0, fcb, 64);
        cudaEventRecord(evB, s2);
        lsm_kernel<<<BB, 1024, 0, s2>>>(dout, t);
    }
    // join side stream back before capture ends
    cudaEventRecord(evEnd, s2);
    cudaStreamWaitEvent(0, evEnd, 0);
}

// round 8
// speedup vs baseline: 4.6384x; 1.4182x over previous
#include <cuda_runtime.h>
#include <cuda_bf16.h>
#include <cstdint>

#define BB 16
#define SS 128
#define TT 64
#define EE 768
#define HH 1024
#define VV 32000

// ---------------- device scratch (static, no allocation) ----------------
__device__ __nv_bfloat16 g_xbf[BB * SS * EE];        // x bf16 (2048,768)
__device__ __nv_bfloat16 g_xprojbf[BB * SS * HH];    // x@Wx + b1, bf16 (2048,1024)
// fragment-packed weights: uint4 per (ntile16, kchunk16, lane)
__device__ uint4 g_pWx[(HH / 16) * (EE / 16) * 32];
__device__ uint4 g_pWh[(HH / 16) * (HH / 16) * 32];
__device__ uint4 g_pWc0[(4096 / 16) * (2560 / 16) * 32];
__device__ uint4 g_pWc1[(4096 / 16) * (2048 / 16) * 32];
__device__ uint4 g_pWc2[(4096 / 16) * (2048 / 16) * 32];
__device__ uint4 g_pFc[(VV / 16) * (HH / 16) * 32];

__device__ __nv_bfloat16 g_A0[BB * 2560];   // [emb | ctx | h0]
__device__ __nv_bfloat16 g_A1[BB * 2048];   // [h0_new | h1_prev]
__device__ __nv_bfloat16 g_A2[BB * 2048];   // [h1_new | h2]
__device__ float         g_c[3 * BB * HH];  // cell states
__device__ float         g_hvp[8 * BB * HH];      // h2@Wh split-K partials
__device__ float         g_part[8 * BB * 4096];   // LSTM gate split-K partials

// ---------------- prologue ----------------
__global__ void prolog_cvt_x(const float* __restrict__ x) {
    int i = blockIdx.x * 256 + threadIdx.x;
    if (i < BB * SS * EE) g_xbf[i] = __float2bfloat16(x[i]);
}

__global__ void pack_all(const float* __restrict__ Wx, const float* __restrict__ Wh,
                         const float* __restrict__ Wih0, const float* __restrict__ Whh0,
                         const float* __restrict__ Wih1, const float* __restrict__ Whh1,
                         const float* __restrict__ Wih2, const float* __restrict__ Whh2,
                         const float* __restrict__ fcW) {
    const long long C0 = 98304, C1 = C0 + 131072, C2 = C1 + 1310720,
                    C3 = C2 + 1048576, C4 = C3 + 1048576, C5 = C4 + 4096000;
    long long idx = (long long)blockIdx.x * 256 + threadIdx.x;
    if (idx >= C5) return;
    uint4* dst; const float *s1, *s2 = nullptr;
    int N, K1, K2 = 0, tr; long long base;
    if (idx < C0)      { dst = g_pWx;  s1 = Wx;   N = HH;   K1 = EE;   tr = 1; base = 0; }
    else if (idx < C1) { dst = g_pWh;  s1 = Wh;   N = HH;   K1 = HH;   tr = 1; base = C0; }
    else if (idx < C2) { dst = g_pWc0; s1 = Wih0; s2 = Whh0; N = 4096; K1 = 1536; K2 = 1024; tr = 0; base = C1; }
    else if (idx < C3) { dst = g_pWc1; s1 = Wih1; s2 = Whh1; N = 4096; K1 = 1024; K2 = 1024; tr = 0; base = C2; }
    else if (idx < C4) { dst = g_pWc2; s1 = Wih2; s2 = Whh2; N = 4096; K1 = 1024; K2 = 1024; tr = 0; base = C3; }
    else               { dst = g_pFc;  s1 = fcW;  N = VV;   K1 = HH;   tr = 0; base = C4; }
    long long li = idx - base;
    int nch = (K1 + K2) >> 4;
    int lane = (int)(li & 31);
    long long tt = li >> 5;
    int ch = (int)(tt % nch);
    int nt = (int)(tt / nch);
    int g = lane >> 2, tig = lane & 3;
    int k = ch * 16 + tig * 2;
    int r0 = nt * 16 + g, r1 = r0 + 8;
    auto ld = [&](int n, int kk) -> float {
        if (kk < K1) return tr ? s1[(long long)kk * N + n] : s1[(long long)n * K1 + kk];
        return s2[(long long)n * HH + (kk - K1)];
    };
    auto p2 = [&](float a, float b) -> unsigned {
        __nv_bfloat162 h = __floats2bfloat162_rn(a, b);
        return *reinterpret_cast<unsigned*>(&h);
    };
    uint4 v;
    v.x = p2(ld(r0, k), ld(r0, k + 1));
    v.y = p2(ld(r0, k + 8), ld(r0, k + 9));
    v.z = p2(ld(r1, k), ld(r1, k + 1));
    v.w = p2(ld(r1, k + 8), ld(r1, k + 9));
    dst[li] = v;
}

__global__ void prolog_zero() {
    int i = blockIdx.x * 256 + threadIdx.x;
    if (i < 3 * BB * HH) g_c[i] = 0.f;
    __nv_bfloat16 z = __float2bfloat16(0.f);
    if (i < BB * HH) {
        int b = i >> 10, j = i & 1023;
        g_A0[b * 2560 + 1536 + j] = z;
    }
    if (i < BB * 2048) { g_A1[i] = z; g_A2[i] = z; }
}

// ---------------- 16xN bf16 tensor-core GEMM v4 ----------------
// n=32 per warp, ldmatrix A-fragments, optional streaming (evict) B loads.
__device__ __forceinline__ const __nv_bfloat16* selA(int t) {
    switch (t) {
        case 0: return g_xbf;
        case 1: return g_A0;
        case 2: return g_A1;
        case 3: return g_A2;
        default: return g_A2 + 1024;  // h2 slice
    }
}

__device__ __forceinline__ void mma16816(float c[4], uint32_t a0, uint32_t a1, uint32_t a2,
                                         uint32_t a3, uint32_t b0, uint32_t b1) {
    asm volatile(
        "mma.sync.aligned.m16n8k16.row.col.f32.bf16.bf16.f32 "
        "{%0,%1,%2,%3}, {%4,%5,%6,%7}, {%8,%9}, {%0,%1,%2,%3};\n"
        : "+f"(c[0]), "+f"(c[1]), "+f"(c[2]), "+f"(c[3])
        : "r"(a0), "r"(a1), "r"(a2), "r"(a3), "r"(b0), "r"(b1));
}

#define APAD 8
#define AMAXC (64 * 16)  // max k-slice per block (fc: 64 chunks)

// cTag: 0 = g_xprojbf (bf16), 1 = g_hvp, 2 = g_part, 3 = external fp32 (dout)
template <bool EF>
__global__ __launch_bounds__(256) void gemm_v4(
    int aTag, int lda, int bTag, int cTag, float* cExt, long long ldc,
    int partStride, const float* __restrict__ bias, int nCh) {
    __shared__ __nv_bfloat16 s_a[16][AMAXC + APAD];
    const __nv_bfloat16* A = selA(aTag);
    const uint4* B;
    int nchTot;
    switch (bTag) {
        case 0: B = g_pWx;  nchTot = EE / 16;   break;
        case 1: B = g_pWh;  nchTot = HH / 16;   break;
        case 2: B = g_pWc0; nchTot = 2560 / 16; break;
        case 3: B = g_pWc1; nchTot = 2048 / 16; break;
        case 4: B = g_pWc2; nchTot = 2048 / 16; break;
        default: B = g_pFc; nchTot = HH / 16;   break;
    }
    int w = threadIdx.x >> 5, lane = threadIdx.x & 31;
    int g = lane >> 2, tig = lane & 3;
    int m0 = blockIdx.y * 16;
    int n0 = blockIdx.x * 256 + w * 32;
    int ch0 = blockIdx.z * nCh;

    // ---- stage A slice (16 x nCh*16) into padded smem, coalesced uint4 ----
    {
        int cols4 = nCh * 2;  // uint4 per row
        for (int idx = threadIdx.x; idx < 16 * cols4; idx += 256) {
            int r = idx / cols4, cc = idx % cols4;
            uint4 v = *reinterpret_cast<const uint4*>(
                A + (long long)(m0 + r) * lda + ch0 * 16 + cc * 8);
            *reinterpret_cast<uint4*>(&s_a[r][cc * 8]) = v;
        }
    }
    __syncthreads();

    const uint4* bp0 = B + ((long long)(n0 >> 4) * nchTot + ch0) * 32 + lane;
    const uint4* bp1 = bp0 + (long long)nchTot * 32;
    // ldmatrix source address: lanes 0-15 -> rows 0-15 @k0, lanes 16-31 -> rows 0-15 @k8
    uint32_t sab = (uint32_t)__cvta_generic_to_shared(
        &s_a[lane & 15][(lane >> 4) * 8]);

    float acc[4][4] = {{0.f}, {0.f}, {0.f}, {0.f}};

#pragma unroll 4
    for (int c = 0; c < nCh; c++) {
        uint4 b0 = EF ? __ldcs(bp0 + (long long)c * 32) : __ldg(bp0 + (long long)c * 32);
        uint4 b1 = EF ? __ldcs(bp1 + (long long)c * 32) : __ldg(bp1 + (long long)c * 32);
        uint32_t a0, a1, a2, a3;
        asm volatile("ldmatrix.sync.aligned.m8n8.x4.shared.b16 {%0,%1,%2,%3}, [%4];"
                     : "=r"(a0), "=r"(a1), "=r"(a2), "=r"(a3)
                     : "r"(sab + (uint32_t)c * 32));
        mma16816(acc[0], a0, a1, a2, a3, b0.x, b0.y);
        mma16816(acc[1], a0, a1, a2, a3, b0.z, b0.w);
        mma16816(acc[2], a0, a1, a2, a3, b1.x, b1.y);
        mma16816(acc[3], a0, a1, a2, a3, b1.z, b1.w);
    }

    int r0 = m0 + g, r1 = m0 + g + 8;
    if (cTag == 0) {
        __nv_bfloat16* Cb = g_xprojbf;
#pragma unroll
        for (int q = 0; q < 4; q++) {
            int col = n0 + q * 8 + tig * 2;
            float bv0 = bias[col], bv1 = bias[col + 1];
            Cb[(long long)r0 * ldc + col]     = __float2bfloat16(acc[q][0] + bv0);
            Cb[(long long)r0 * ldc + col + 1] = __float2bfloat16(acc[q][1] + bv1);
            Cb[(long long)r1 * ldc + col]     = __float2bfloat16(acc[q][2] + bv0);
            Cb[(long long)r1 * ldc + col + 1] = __float2bfloat16(acc[q][3] + bv1);
        }
        return;
    }
    float* C = (cTag == 1) ? g_hvp : (cTag == 2) ? g_part : cExt;
    C += (long long)blockIdx.z * partStride;
#pragma unroll
    for (int q = 0; q < 4; q++) {
        int col = n0 + q * 8 + tig * 2;
        float bv0 = bias ? bias[col] : 0.f, bv1 = bias ? bias[col + 1] : 0.f;
        C[(long long)r0 * ldc + col]     = acc[q][0] + bv0;
        C[(long long)r0 * ldc + col + 1] = acc[q][1] + bv1;
        C[(long long)r1 * ldc + col]     = acc[q][2] + bv0;
        C[(long long)r1 * ldc + col + 1] = acc[q][3] + bv1;
    }
}

// ---------------- fused attention ----------------
__global__ __launch_bounds__(1024) void attn_fused(
    const float* __restrict__ w2, const float* __restrict__ b2,
    const int* __restrict__ tseq, const float* __restrict__ emb, int t) {
    __shared__ float hv_s[HH];
    __shared__ float w2_s[HH];
    __shared__ float sc[SS];
    __shared__ float bc;
    int b = blockIdx.x, tid = threadIdx.x;
    {
        float s = 0.f;
#pragma unroll
        for (int p = 0; p < 8; p++) s += g_hvp[p * BB * HH + b * HH + tid];
        hv_s[tid] = s;
        w2_s[tid] = w2[tid];
    }
    __syncthreads();
    int w = tid >> 5, lane = tid & 31;
#pragma unroll
    for (int rr = 0; rr < 4; rr++) {
        int s = w + rr * 32;
        const __nv_bfloat16* row = g_xprojbf + ((long long)b * SS + s) * HH;
        float sum = 0.f;
#pragma unroll
        for (int it = 0; it < 4; it++) {
            int k0 = it * 256 + lane * 8;
            uint4 v = *reinterpret_cast<const uint4*>(row + k0);
            const __nv_bfloat162* hp = reinterpret_cast<const __nv_bfloat162*>(&v);
#pragma unroll
            for (int j = 0; j < 4; j++) {
                float2 f = __bfloat1622float2(hp[j]);
                int k = k0 + j * 2;
                float a = f.x + hv_s[k];
                float c = f.y + hv_s[k + 1];
                sum += (a > 0.f ? a * w2_s[k] : 0.f) + (c > 0.f ? c * w2_s[k + 1] : 0.f);
            }
        }
#pragma unroll
        for (int o = 16; o; o >>= 1) sum += __shfl_xor_sync(0xffffffffu, sum, o);
        if (!lane) sc[s] = sum + b2[0];
    }
    __syncthreads();
    if (w == 0) {
        float m = -1e30f;
#pragma unroll
        for (int i = 0; i < 4; i++) m = fmaxf(m, sc[lane + i * 32]);
#pragma unroll
        for (int o = 16; o; o >>= 1) m = fmaxf(m, __shfl_xor_sync(0xffffffffu, m, o));
        float su = 0.f;
#pragma unroll
        for (int i = 0; i < 4; i++) su += expf(sc[lane + i * 32] - m);
#pragma unroll
        for (int o = 16; o; o >>= 1) su += __shfl_xor_sync(0xffffffffu, su, o);
        if (!lane) bc = m + logf(su);
    }
    __syncthreads();
    float lse = bc;
    if (tid < SS) sc[tid] -= lse;
    __syncthreads();
    if (tid < EE) {
        const __nv_bfloat16* xb = g_xbf + (long long)b * SS * EE + tid;
        float acc = 0.f;
#pragma unroll 8
        for (int s = 0; s < SS; s++) acc += sc[s] * __bfloat162float(xb[(long long)s * EE]);
        g_A0[b * 2560 + EE + tid] = __float2bfloat16(acc);
        int tok = tseq[b * TT + t];
        g_A0[b * 2560 + tid] = __float2bfloat16(emb[(long long)tok * EE + tid]);
    }
}

// ---------------- LSTM cell elementwise (sums 8 split-K partials) ----------------
__global__ __launch_bounds__(256) void lstm_cell(
    const float* __restrict__ bih, const float* __restrict__ bhh, int layer) {
    int idx = blockIdx.x * 256 + threadIdx.x;  // 16384
    int b = idx >> 10, j = idx & 1023;
    float gi = bih[j] + bhh[j];
    float gf = bih[1024 + j] + bhh[1024 + j];
    float gg = bih[2048 + j] + bhh[2048 + j];
    float go = bih[3072 + j] + bhh[3072 + j];
#pragma unroll
    for (int p = 0; p < 8; p++) {
        const float* pp = g_part + p * (BB * 4096) + b * 4096;
        gi += pp[j];
        gf += pp[1024 + j];
        gg += pp[2048 + j];
        go += pp[3072 + j];
    }
    float si = 1.f / (1.f + expf(-gi));
    float sf = 1.f / (1.f + expf(-gf));
    float so = 1.f / (1.f + expf(-go));
    float* cc = g_c + layer * (BB * HH) + idx;
    float cn = sf * (*cc) + si * tanhf(gg);
    *cc = cn;
    float h = so * tanhf(cn);
    __nv_bfloat16 hb = __float2bfloat16(h);
    if (layer == 0) {
        g_A1[b * 2048 + j] = hb;
        g_A0[b * 2560 + 1536 + j] = hb;
    } else if (layer == 1) {
        g_A2[b * 2048 + j] = hb;
        g_A1[b * 2048 + 1024 + j] = hb;
    } else {
        g_A2[b * 2048 + 1024 + j] = hb;
    }
}

// ---------------- in-place log_softmax over V (float4) ----------------
__global__ __launch_bounds__(1024) void lsm_kernel(float* __restrict__ dout, int t) {
    float4* row = reinterpret_cast<float4*>(dout + (long long)blockIdx.x * TT * VV +
                                            (long long)t * VV);
    const int NV4 = VV / 4;  // 8000
    __shared__ float sm[32];
    __shared__ float bc;
    int tid = threadIdx.x, lane = tid & 31, wid = tid >> 5;
    float m = -1e30f;
    for (int i = tid; i < NV4; i += 1024) {
        float4 v = row[i];
        m = fmaxf(m, fmaxf(fmaxf(v.x, v.y), fmaxf(v.z, v.w)));
    }
#pragma unroll
    for (int o = 16; o; o >>= 1) m = fmaxf(m, __shfl_xor_sync(0xffffffffu, m, o));
    if (!lane) sm[wid] = m;
    __syncthreads();
    if (tid < 32) {
        float mm = sm[tid];
#pragma unroll
        for (int o = 16; o; o >>= 1) mm = fmaxf(mm, __shfl_xor_sync(0xffffffffu, mm, o));
        if (!tid) bc = mm;
    }
    __syncthreads();
    m = bc;
    float s = 0.f;
    for (int i = tid; i < NV4; i += 1024) {
        float4 v = row[i];
        s += expf(v.x - m) + expf(v.y - m) + expf(v.z - m) + expf(v.w - m);
    }
#pragma unroll
    for (int o = 16; o; o >>= 1) s += __shfl_xor_sync(0xffffffffu, s, o);
    __syncthreads();
    if (!lane) sm[wid] = s;
    __syncthreads();
    if (tid < 32) {
        float ss = sm[tid];
#pragma unroll
        for (int o = 16; o; o >>= 1) ss += __shfl_xor_sync(0xffffffffu, ss, o);
        if (!tid) bc = m + logf(ss);
    }
    __syncthreads();
    float lse = bc;
    for (int i = tid; i < NV4; i += 1024) {
        float4 v = row[i];
        v.x -= lse; v.y -= lse; v.z -= lse; v.w -= lse;
        row[i] = v;
    }
}

// ---------------- host launch ----------------
extern "C" void kernel_launch(void* const* d_in, const int* in_sizes, int n_in,
                              void* d_out, int out_size) {
    const float* x    = (const float*)d_in[0];
    const int*   tseq = (const int*)d_in[1];
    const float* emb  = (const float*)d_in[2];
    const float* Wx   = (const float*)d_in[3];
    const float* Wh   = (const float*)d_in[4];
    const float* b1   = (const float*)d_in[5];
    const float* w2   = (const float*)d_in[6];
    const float* b2   = (const float*)d_in[7];
    const float* fcW  = (const float*)d_in[8];
    const float* fcb  = (const float*)d_in[9];
    const float* Wih0 = (const float*)d_in[10];
    const float* Whh0 = (const float*)d_in[11];
    const float* bih0 = (const float*)d_in[12];
    const float* bhh0 = (const float*)d_in[13];
    const float* Wih1 = (const float*)d_in[14];
    const float* Whh1 = (const float*)d_in[15];
    const float* bih1 = (const float*)d_in[16];
    const float* bhh1 = (const float*)d_in[17];
    const float* Wih2 = (const float*)d_in[18];
    const float* Whh2 = (const float*)d_in[19];
    const float* bih2 = (const float*)d_in[20];
    const float* bhh2 = (const float*)d_in[21];
    float* dout = (float*)d_out;

    static cudaStream_t s2 = nullptr;
    static cudaEvent_t evA = nullptr, evB = nullptr, evEnd = nullptr;
    if (!s2) {
        cudaStreamCreateWithFlags(&s2, cudaStreamNonBlocking);
        cudaEventCreateWithFlags(&evA, cudaEventDisableTiming);
        cudaEventCreateWithFlags(&evB, cudaEventDisableTiming);
        cudaEventCreateWithFlags(&evEnd, cudaEventDisableTiming);
    }

    // -------- prologue --------
    prolog_cvt_x<<<(BB * SS * EE + 255) / 256, 256>>>(x);
    pack_all<<<30208, 256>>>(Wx, Wh, Wih0, Whh0, Wih1, Whh1, Wih2, Whh2, fcW);
    prolog_zero<<<(3 * BB * HH + 255) / 256, 256>>>();
    // x_proj (bf16 out): M=2048, N=1024 (4 nblocks), K=768 (48 chunks)
    gemm_v4<false><<<dim3(4, 128, 1), 256>>>(0, EE, 0, 0, nullptr, HH, 0, b1, 48);

    // -------- time loop --------
    for (int t = 0; t < TT; t++) {
        // hv = h2 @ Wh : N=1024 (4 nblocks), split-K=8 (8 chunks each)
        gemm_v4<false><<<dim3(4, 1, 8), 256>>>(4, 2048, 1, 1, nullptr, HH, BB * HH,
                                               nullptr, 8);
        attn_fused<<<BB, 1024>>>(w2, b2, tseq, emb, t);
        // layer 0: N=4096 (16 nblocks), K=2560 split-K=8 (20 chunks each)
        gemm_v4<false><<<dim3(16, 1, 8), 256>>>(1, 2560, 2, 2, nullptr, 4096, BB * 4096,
                                                nullptr, 20);
        lstm_cell<<<64, 256>>>(bih0, bhh0, 0);
        // layer 1: K=2048 split-K=8 (16 chunks each)
        gemm_v4<false><<<dim3(16, 1, 8), 256>>>(2, 2048, 3, 2, nullptr, 4096, BB * 4096,
                                                nullptr, 16);
        lstm_cell<<<64, 256>>>(bih1, bhh1, 1);
        // layer 2
        gemm_v4<false><<<dim3(16, 1, 8), 256>>>(3, 2048, 4, 2, nullptr, 4096, BB * 4096,
                                                nullptr, 16);
        // cell2 overwrites h2 -> must wait for previous step's fc (reads h2)
        if (t > 0) cudaStreamWaitEvent(0, evB, 0);
        lstm_cell<<<64, 256>>>(bih2, bhh2, 2);

        // fork fc + lsm onto side stream (depends only on cell2 of this step)
        cudaEventRecord(evA, 0);
        cudaStreamWaitEvent(s2, evA, 0);
        // fc: N=32000 (125 nblocks), K=1024 (64 chunks), streaming weights
        gemm_v4<true><<<dim3(125, 1, 1), 256, 0, s2>>>(4, 2048, 5, 3,
                                                       dout + (long long)t * VV,
                                                       (long long)TT * VV, 0, fcb, 64);
        cudaEventRecord(evB, s2);
        lsm_kernel<<<BB, 1024, 0, s2>>>(dout, t);
    }
    // join side stream back before capture ends
    cudaEventRecord(evEnd, s2);
    cudaStreamWaitEvent(0, evEnd, 0);
}